// round 8
// baseline (speedup 1.0000x reference)
#include <cuda_runtime.h>
#include <cuda_bf16.h>
#include <cstdint>

// Problem constants (fixed by the dataset)
#define NMAX   50000
#define EMAX   800000
#define OUT_D  128
#define DIN    256
#define NVS    256
#define NATT   16

// ---------------------------------------------------------------------------
// Device scratch
// ---------------------------------------------------------------------------
__device__ float    d_bvs[NVS];
__device__ float    d_batt[NATT];
__device__ float    d_atte[EMAX * 8];
__device__ float    d_vs[NMAX * NVS];
__device__ float    d_att[NMAX * NATT];
__device__ float    d_hidden1[NMAX * OUT_D];
__device__ int      d_deg[NMAX];
__device__ int      d_off[NMAX + 1];
__device__ int      d_cursor[NMAX];
__device__ int      d_csrcol[EMAX];
__device__ float    d_logits[EMAX * 8];
__device__ unsigned d_rowmax[NMAX * 8];

// split-bf16 operands for the tensor-core GEMMs
__device__ __nv_bfloat16 d_zhi[NMAX * DIN];
__device__ __nv_bfloat16 d_zlo[NMAX * DIN];
__device__ __nv_bfloat16 d_Wbhi[NVS * DIN];
__device__ __nv_bfloat16 d_Wblo[NVS * DIN];
__device__ __nv_bfloat16 d_Wathi[NATT * DIN];   // att weights, [n][k]
__device__ __nv_bfloat16 d_Watlo[NATT * DIN];

// ---------------------------------------------------------------------------
// Helpers
// ---------------------------------------------------------------------------
__device__ __forceinline__ uint32_t smem_u32(const void* p) {
    uint32_t a;
    asm("{ .reg .u64 t; cvta.to.shared.u64 t, %1; cvt.u32.u64 %0, t; }" : "=r"(a) : "l"(p));
    return a;
}

__device__ __forceinline__ void ldsm4(uint32_t* r, uint32_t addr) {
    asm volatile("ldmatrix.sync.aligned.m8n8.x4.shared.b16 {%0,%1,%2,%3}, [%4];"
                 : "=r"(r[0]), "=r"(r[1]), "=r"(r[2]), "=r"(r[3]) : "r"(addr));
}

__device__ __forceinline__ void mma16816(float* c, const uint32_t* a, uint32_t b0, uint32_t b1) {
    asm volatile("mma.sync.aligned.m16n8k16.row.col.f32.bf16.bf16.f32 "
                 "{%0,%1,%2,%3}, {%4,%5,%6,%7}, {%8,%9}, {%0,%1,%2,%3};"
                 : "+f"(c[0]), "+f"(c[1]), "+f"(c[2]), "+f"(c[3])
                 : "r"(a[0]), "r"(a[1]), "r"(a[2]), "r"(a[3]), "r"(b0), "r"(b1));
}

__device__ __forceinline__ unsigned fenc(float f) {
    unsigned u = __float_as_uint(f);
    return (u & 0x80000000u) ? ~u : (u | 0x80000000u);
}
__device__ __forceinline__ float fdec(unsigned u) {
    return (u & 0x80000000u) ? __uint_as_float(u & 0x7FFFFFFFu)
                             : __uint_as_float(~u);
}

// ---------------------------------------------------------------------------
// Weight prep
// ---------------------------------------------------------------------------
__global__ void pack_bias_kernel(const float* __restrict__ bm, const float* __restrict__ bsk,
                                 const float* __restrict__ ba1, const float* __restrict__ ba2) {
    int i = blockIdx.x * blockDim.x + threadIdx.x;
    if (i < NVS)  d_bvs[i]  = (i < 128) ? bm[i] : bsk[i - 128];
    if (i < NATT) d_batt[i] = (i < 8) ? ba1[i] : ba2[i - 8];
}

__global__ void pack_weights_bf16_kernel(const float* __restrict__ Wm,
                                         const float* __restrict__ Wsk,
                                         const float* __restrict__ Wa1,
                                         const float* __restrict__ Wa2) {
    int i = blockIdx.x * blockDim.x + threadIdx.x;     // i = n*256 + k
    if (i < NVS * DIN) {
        int n = i >> 8, k = i & 255;
        float w = (n < 128) ? Wm[k * 128 + n] : Wsk[k * 128 + (n - 128)];
        __nv_bfloat16 hi = __float2bfloat16(w);
        __nv_bfloat16 lo = __float2bfloat16(w - __bfloat162float(hi));
        d_Wbhi[i] = hi;
        d_Wblo[i] = lo;
    }
    if (i < NATT * DIN) {
        int n = i >> 8, k = i & 255;
        float w = (n < 8) ? Wa1[k * 8 + n] : Wa2[k * 8 + (n - 8)];
        __nv_bfloat16 hi = __float2bfloat16(w);
        __nv_bfloat16 lo = __float2bfloat16(w - __bfloat162float(hi));
        d_Wathi[i] = hi;
        d_Watlo[i] = lo;
    }
}

// Convert a 128-wide fp32 node array into half of z (hi/lo split).
__global__ void convert_half_kernel(const float* __restrict__ src, int M, int half_off) {
    int idx = blockIdx.x * blockDim.x + threadIdx.x;
    if (idx >= M * 32) return;
    int row = idx >> 5, c4 = (idx & 31) * 4;
    float4 v = *(const float4*)&src[(size_t)row * 128 + c4];
    __nv_bfloat16 h[4], l[4];
    float f[4] = {v.x, v.y, v.z, v.w};
#pragma unroll
    for (int j = 0; j < 4; j++) {
        h[j] = __float2bfloat16(f[j]);
        l[j] = __float2bfloat16(f[j] - __bfloat162float(h[j]));
    }
    size_t o = (size_t)row * 256 + half_off + c4;
    *(uint2*)&d_zhi[o] = *(uint2*)h;
    *(uint2*)&d_zlo[o] = *(uint2*)l;
}

// ---------------------------------------------------------------------------
// Tensor GEMM via mma.sync, producing d_vs + d_att (fused), unchanged from R6.
// ---------------------------------------------------------------------------
#define SSTR 72
#define SROWB (SSTR * 2)
#define OFF_AHI 0
#define OFF_ALO (128 * SROWB)
#define OFF_BHI (2 * 128 * SROWB)
#define OFF_BLO (3 * 128 * SROWB)
#define OFF_WHI (4 * 128 * SROWB)
#define OFF_WLO (OFF_WHI + 16 * SROWB)
#define GEMM_SMEM (OFF_WLO + 16 * SROWB)

__global__ __launch_bounds__(256, 1)
void gemm_vs_mma_kernel(int M) {
    extern __shared__ char smem[];
    uint32_t sb = smem_u32(smem);
    int t = threadIdx.x, wid = t >> 5, lane = t & 31;
    int warp_m = wid & 1, warp_n = wid >> 1;
    int row0 = blockIdx.x * 128, col0 = blockIdx.y * 128;
    bool blk_att = (blockIdx.y == 0);
    bool do_att = blk_att && (warp_n < 2);

    float acc[4][4][4];
#pragma unroll
    for (int a = 0; a < 4; a++)
#pragma unroll
        for (int b = 0; b < 4; b++)
#pragma unroll
            for (int c = 0; c < 4; c++) acc[a][b][c] = 0.f;
    float acc_att[4][4];
#pragma unroll
    for (int a = 0; a < 4; a++)
#pragma unroll
        for (int c = 0; c < 4; c++) acc_att[a][c] = 0.f;

    int lrow = lane & 15;
    int lcol = (lane >> 4) * 8;

    for (int kc = 0; kc < 4; kc++) {
        if (kc) __syncthreads();
        int kbase = kc * 64;
#pragma unroll
        for (int i = 0; i < 4; i++) {
            int idx = t + i * 256;
            int r = idx >> 3, k8 = (idx & 7) * 8;
            int grow = row0 + r;
            uint4 ahi = make_uint4(0, 0, 0, 0), alo = ahi;
            if (grow < M) {
                ahi = *(const uint4*)&d_zhi[(size_t)grow * 256 + kbase + k8];
                alo = *(const uint4*)&d_zlo[(size_t)grow * 256 + kbase + k8];
            }
            *(uint4*)(smem + OFF_AHI + r * SROWB + k8 * 2) = ahi;
            *(uint4*)(smem + OFF_ALO + r * SROWB + k8 * 2) = alo;
            int n = col0 + r;
            *(uint4*)(smem + OFF_BHI + r * SROWB + k8 * 2) =
                *(const uint4*)&d_Wbhi[(size_t)n * 256 + kbase + k8];
            *(uint4*)(smem + OFF_BLO + r * SROWB + k8 * 2) =
                *(const uint4*)&d_Wblo[(size_t)n * 256 + kbase + k8];
        }
        if (blk_att) {
            int r = (t >> 3) & 15, k8 = (t & 7) * 8;
            const __nv_bfloat16* src = (t < 128) ? d_Wathi : d_Watlo;
            int off = (t < 128) ? OFF_WHI : OFF_WLO;
            *(uint4*)(smem + off + r * SROWB + k8 * 2) =
                *(const uint4*)&src[(size_t)r * 256 + kbase + k8];
        }
        __syncthreads();

#pragma unroll
        for (int ks = 0; ks < 4; ks++) {
            int kofs = (ks * 16 + lcol) * 2;
            uint32_t ahi[4][4], alo[4][4];
#pragma unroll
            for (int mi = 0; mi < 4; mi++) {
                uint32_t arow = (uint32_t)(warp_m * 64 + mi * 16 + lrow);
                ldsm4(ahi[mi], sb + OFF_AHI + arow * SROWB + kofs);
                ldsm4(alo[mi], sb + OFF_ALO + arow * SROWB + kofs);
            }
            uint32_t bhi[2][4], blo[2][4];
#pragma unroll
            for (int nj = 0; nj < 2; nj++) {
                uint32_t brow = (uint32_t)(warp_n * 32 + nj * 16 + lrow);
                ldsm4(bhi[nj], sb + OFF_BHI + brow * SROWB + kofs);
                ldsm4(blo[nj], sb + OFF_BLO + brow * SROWB + kofs);
            }
#pragma unroll
            for (int mi = 0; mi < 4; mi++) {
#pragma unroll
                for (int ni = 0; ni < 4; ni++) {
                    int nj = ni >> 1, pr = ni & 1;
                    uint32_t bh0 = bhi[nj][pr], bh1 = bhi[nj][pr + 2];
                    uint32_t bl0 = blo[nj][pr], bl1 = blo[nj][pr + 2];
                    mma16816(acc[mi][ni], ahi[mi], bh0, bh1);
                    mma16816(acc[mi][ni], ahi[mi], bl0, bl1);
                    mma16816(acc[mi][ni], alo[mi], bh0, bh1);
                }
            }
            if (do_att) {
                uint32_t whi[4], wlo[4];
                ldsm4(whi, sb + OFF_WHI + (uint32_t)lrow * SROWB + kofs);
                ldsm4(wlo, sb + OFF_WLO + (uint32_t)lrow * SROWB + kofs);
                uint32_t wh0 = whi[warp_n], wh1 = whi[warp_n + 2];
                uint32_t wl0 = wlo[warp_n], wl1 = wlo[warp_n + 2];
#pragma unroll
                for (int mi = 0; mi < 4; mi++) {
                    mma16816(acc_att[mi], ahi[mi], wh0, wh1);
                    mma16816(acc_att[mi], ahi[mi], wl0, wl1);
                    mma16816(acc_att[mi], alo[mi], wh0, wh1);
                }
            }
        }
    }

#pragma unroll
    for (int mi = 0; mi < 4; mi++) {
        int rA = row0 + warp_m * 64 + mi * 16 + (lane >> 2);
        int rB = rA + 8;
#pragma unroll
        for (int ni = 0; ni < 4; ni++) {
            int col = col0 + warp_n * 32 + ni * 8 + (lane & 3) * 2;
            float2 bias = *(const float2*)&d_bvs[col];
            if (rA < M) {
                float2 o = make_float2(acc[mi][ni][0] + bias.x, acc[mi][ni][1] + bias.y);
                *(float2*)&d_vs[(size_t)rA * 256 + col] = o;
            }
            if (rB < M) {
                float2 o = make_float2(acc[mi][ni][2] + bias.x, acc[mi][ni][3] + bias.y);
                *(float2*)&d_vs[(size_t)rB * 256 + col] = o;
            }
        }
        if (do_att) {
            int col = warp_n * 8 + (lane & 3) * 2;
            float2 bias = *(const float2*)&d_batt[col];
            if (rA < M) {
                float2 o = make_float2(acc_att[mi][0] + bias.x, acc_att[mi][1] + bias.y);
                *(float2*)&d_att[(size_t)rA * 16 + col] = o;
            }
            if (rB < M) {
                float2 o = make_float2(acc_att[mi][2] + bias.x, acc_att[mi][3] + bias.y);
                *(float2*)&d_att[(size_t)rB * 16 + col] = o;
            }
        }
    }
}

// ---------------------------------------------------------------------------
// Edge-feature attention v3: warp per edge, no SMEM, fold-reduction.
// Lane owns k = lane*4..lane*4+3; 1 coalesced LDG.128 per lane per edge
// (each input byte read exactly once). 8 head-partials per lane, then
// send-half/keep-half butterfly (9 shfl) -> head (lane>>2)&7 reduced.
// ---------------------------------------------------------------------------
#define EA_UNROLL 4

__global__ __launch_bounds__(256)
void edge_att_kernel(const float* __restrict__ efts,
                     const float* __restrict__ Wae,
                     const float* __restrict__ bae, int E) {
    int lane = threadIdx.x & 31;
    int k0 = lane * 4;

    float wf[32];   // wf[i*8+h] = Wae[(k0+i)*8 + h]
#pragma unroll
    for (int i = 0; i < 4; i++)
#pragma unroll
        for (int h = 0; h < 8; h++)
            wf[i * 8 + h] = Wae[(k0 + i) * 8 + h];
    int myh = (lane >> 2) & 7;
    float b = bae[myh];

    int warp0 = (blockIdx.x * blockDim.x + threadIdx.x) >> 5;
    int nw = (gridDim.x * blockDim.x) >> 5;

    const float4* ef4 = (const float4*)efts;

    for (int e0 = warp0 * EA_UNROLL; e0 < E; e0 += nw * EA_UNROLL) {
        float4 v[EA_UNROLL];
#pragma unroll
        for (int j = 0; j < EA_UNROLL; j++) {
            int e = e0 + j;
            v[j] = (e < E) ? ef4[(size_t)e * 32 + lane]
                           : make_float4(0.f, 0.f, 0.f, 0.f);
        }
#pragma unroll
        for (int j = 0; j < EA_UNROLL; j++) {
            int e = e0 + j;
            float acc[8];
#pragma unroll
            for (int h = 0; h < 8; h++) {
                acc[h] = v[j].x * wf[h] + v[j].y * wf[8 + h]
                       + v[j].z * wf[16 + h] + v[j].w * wf[24 + h];
            }
            // stage 1: xor 16, keep 4 (head bit 2 <- lane bit 4)
            bool hi16 = (lane & 16) != 0;
#pragma unroll
            for (int i = 0; i < 4; i++) {
                float send = hi16 ? acc[i] : acc[i + 4];
                float recv = __shfl_xor_sync(0xffffffffu, send, 16);
                acc[i] = (hi16 ? acc[i + 4] : acc[i]) + recv;
            }
            // stage 2: xor 8, keep 2 (head bit 1 <- lane bit 3)
            bool hi8 = (lane & 8) != 0;
#pragma unroll
            for (int i = 0; i < 2; i++) {
                float send = hi8 ? acc[i] : acc[i + 2];
                float recv = __shfl_xor_sync(0xffffffffu, send, 8);
                acc[i] = (hi8 ? acc[i + 2] : acc[i]) + recv;
            }
            // stage 3: xor 4, keep 1 (head bit 0 <- lane bit 2)
            bool hi4 = (lane & 4) != 0;
            {
                float send = hi4 ? acc[0] : acc[1];
                float recv = __shfl_xor_sync(0xffffffffu, send, 4);
                acc[0] = (hi4 ? acc[1] : acc[0]) + recv;
            }
            // stages 4,5: plain adds across remaining lane bits
            acc[0] += __shfl_xor_sync(0xffffffffu, acc[0], 2);
            acc[0] += __shfl_xor_sync(0xffffffffu, acc[0], 1);

            if ((lane & 3) == 0 && e < E)
                d_atte[(size_t)e * 8 + myh] = acc[0] + b;
        }
    }
}

// ---------------------------------------------------------------------------
// CSR build helpers
// ---------------------------------------------------------------------------
__global__ void zero_init_kernel(int M) {
    int i = blockIdx.x * blockDim.x + threadIdx.x;
    if (i < M) d_deg[i] = 0;
    if (i < M * 8) d_rowmax[i] = 0u;
}

__global__ void count_kernel(const int* __restrict__ idx, int E) {
    int e = blockIdx.x * blockDim.x + threadIdx.x;
    if (e >= E) return;
    int2 rc = ((const int2*)idx)[e];
    atomicAdd(&d_deg[rc.x], 1);
}

__global__ void scan_kernel(int n) {
    __shared__ int wsum[32];
    __shared__ int tot_s;
    int t = threadIdx.x, lane = t & 31, wid = t >> 5;
    int carry = 0;
    for (int base = 0; base < n; base += 1024) {
        int i = base + t;
        int x = (i < n) ? d_deg[i] : 0;
        int v = x;
#pragma unroll
        for (int d = 1; d < 32; d <<= 1) {
            int u = __shfl_up_sync(0xffffffffu, v, d);
            if (lane >= d) v += u;
        }
        if (lane == 31) wsum[wid] = v;
        __syncthreads();
        if (wid == 0) {
            int s = wsum[lane];
            int sv = s;
#pragma unroll
            for (int d = 1; d < 32; d <<= 1) {
                int u = __shfl_up_sync(0xffffffffu, sv, d);
                if (lane >= d) sv += u;
            }
            wsum[lane] = sv - s;
            if (lane == 31) tot_s = sv;
        }
        __syncthreads();
        int excl = carry + wsum[wid] + (v - x);
        if (i < n) { d_off[i] = excl; d_cursor[i] = excl; }
        carry += tot_s;
        __syncthreads();
    }
    if (t == 0) d_off[n] = carry;
}

// ---------------------------------------------------------------------------
// Scatter + logits
// ---------------------------------------------------------------------------
__global__ void scatter_logits_kernel(const int* __restrict__ idx, int E, int use_atte) {
    int e = blockIdx.x * blockDim.x + threadIdx.x;
    if (e >= E) return;
    int2 rc = ((const int2*)idx)[e];
    int row = rc.x, col = rc.y;
    int pos = atomicAdd(&d_cursor[row], 1);
    d_csrcol[pos] = col;
    const float4* pa = (const float4*)&d_att[(size_t)row * 16];
    const float4* pb = (const float4*)&d_att[(size_t)col * 16 + 8];
    float4 a0 = pa[0], a1 = pa[1];
    float4 b0 = pb[0], b1 = pb[1];
    float lg[8] = {a0.x + b0.x, a0.y + b0.y, a0.z + b0.z, a0.w + b0.w,
                   a1.x + b1.x, a1.y + b1.y, a1.z + b1.z, a1.w + b1.w};
    if (use_atte) {
        const float4* pe = (const float4*)&d_atte[(size_t)e * 8];
        float4 e0 = pe[0], e1 = pe[1];
        lg[0] += e0.x; lg[1] += e0.y; lg[2] += e0.z; lg[3] += e0.w;
        lg[4] += e1.x; lg[5] += e1.y; lg[6] += e1.z; lg[7] += e1.w;
    }
#pragma unroll
    for (int h = 0; h < 8; h++) {
        float u = lg[h];
        u = (u > 0.f) ? u : 0.01f * u;
        lg[h] = u;
        atomicMax(&d_rowmax[(size_t)row * 8 + h], fenc(u));
    }
    *(float4*)&d_logits[(size_t)pos * 8]     = make_float4(lg[0], lg[1], lg[2], lg[3]);
    *(float4*)&d_logits[(size_t)pos * 8 + 4] = make_float4(lg[4], lg[5], lg[6], lg[7]);
}

// ---------------------------------------------------------------------------
// Aggregate: warp per row; optionally writes bf16 hi/lo z-half (pass 1).
// ---------------------------------------------------------------------------
__global__ __launch_bounds__(256)
void aggregate_kernel(float* __restrict__ outp, int M, int write_z) {
    int warp = (blockIdx.x * blockDim.x + threadIdx.x) >> 5;
    if (warp >= M) return;
    int lane = threadIdx.x & 31;
    int c0 = lane * 4;
    int h = lane >> 2;
    float mx = fdec(d_rowmax[(size_t)warp * 8 + h]);
    int p = d_off[warp], pend = d_off[warp + 1];
    float s = 0.f;
    float4 acc = make_float4(0.f, 0.f, 0.f, 0.f);
    for (; p < pend; ++p) {
        int col = d_csrcol[p];
        float w = __expf(d_logits[(size_t)p * 8 + h] - mx);
        float4 v = *(const float4*)&d_vs[(size_t)col * 256 + c0];
        s += w;
        acc.x += w * v.x; acc.y += w * v.y; acc.z += w * v.z; acc.w += w * v.w;
    }
    float4 sk = *(const float4*)&d_vs[(size_t)warp * 256 + 128 + c0];
    float inv = (s > 0.f) ? (1.f / s) : 0.f;
    float4 o;
    o.x = fmaxf(acc.x * inv + sk.x, 0.f);
    o.y = fmaxf(acc.y * inv + sk.y, 0.f);
    o.z = fmaxf(acc.z * inv + sk.z, 0.f);
    o.w = fmaxf(acc.w * inv + sk.w, 0.f);
    *(float4*)&outp[(size_t)warp * 128 + c0] = o;
    if (write_z) {
        float f[4] = {o.x, o.y, o.z, o.w};
        __nv_bfloat16 hh[4], ll[4];
#pragma unroll
        for (int jj = 0; jj < 4; jj++) {
            hh[jj] = __float2bfloat16(f[jj]);
            ll[jj] = __float2bfloat16(f[jj] - __bfloat162float(hh[jj]));
        }
        size_t zo = (size_t)warp * 256 + 128 + c0;
        *(uint2*)&d_zhi[zo] = *(uint2*)hh;
        *(uint2*)&d_zlo[zo] = *(uint2*)ll;
    }
}

// ---------------------------------------------------------------------------
// Launch
// ---------------------------------------------------------------------------
extern "C" void kernel_launch(void* const* d_in, const int* in_sizes, int n_in,
                              void* d_out, int out_size) {
    const float* node_fts = (const float*)d_in[0];
    const float* gkt_efts = (const float*)d_in[1];
    const float* hidden   = (const float*)d_in[2];
    const int*   cfg_idx  = (const int*)d_in[3];
    const int*   gkt_idx  = (const int*)d_in[4];
    const float* W_m    = (const float*)d_in[5];
    const float* b_m    = (const float*)d_in[6];
    const float* W_skip = (const float*)d_in[7];
    const float* b_skip = (const float*)d_in[8];
    const float* W_a1   = (const float*)d_in[9];
    const float* b_a1   = (const float*)d_in[10];
    const float* W_a2   = (const float*)d_in[11];
    const float* b_a2   = (const float*)d_in[12];
    const float* W_ae   = (const float*)d_in[13];
    const float* b_ae   = (const float*)d_in[14];
    float* out = (float*)d_out;

    int M  = in_sizes[0] / 128;
    int Ec = in_sizes[3] / 2;
    int Eg = in_sizes[4] / 2;

    float* hid1 = nullptr;
    cudaGetSymbolAddress((void**)&hid1, d_hidden1);

    cudaFuncSetAttribute(gemm_vs_mma_kernel,
                         cudaFuncAttributeMaxDynamicSharedMemorySize, GEMM_SMEM);

    pack_bias_kernel<<<1, 256>>>(b_m, b_skip, b_a1, b_a2);
    pack_weights_bf16_kernel<<<(NVS * DIN + 255) / 256, 256>>>(W_m, W_skip, W_a1, W_a2);
    convert_half_kernel<<<(M * 32 + 255) / 256, 256>>>(node_fts, M, 0);
    edge_att_kernel<<<3552, 256>>>(gkt_efts, W_ae, b_ae, Eg);

    dim3 ggrid((M + 127) / 128, 2);

    // ---- pass 1 (cfg) ----
    convert_half_kernel<<<(M * 32 + 255) / 256, 256>>>(hidden, M, 128);
    gemm_vs_mma_kernel<<<ggrid, 256, GEMM_SMEM>>>(M);    // vs + att fused
    zero_init_kernel<<<(M * 8 + 255) / 256, 256>>>(M);
    count_kernel<<<(Ec + 255) / 256, 256>>>(cfg_idx, Ec);
    scan_kernel<<<1, 1024>>>(M);
    scatter_logits_kernel<<<(Ec + 255) / 256, 256>>>(cfg_idx, Ec, 0);
    aggregate_kernel<<<(M + 7) / 8, 256>>>(hid1, M, 1);

    // ---- pass 2 (gkt) ----
    gemm_vs_mma_kernel<<<ggrid, 256, GEMM_SMEM>>>(M);    // vs + att fused
    zero_init_kernel<<<(M * 8 + 255) / 256, 256>>>(M);
    count_kernel<<<(Eg + 255) / 256, 256>>>(gkt_idx, Eg);
    scan_kernel<<<1, 1024>>>(M);
    scatter_logits_kernel<<<(Eg + 255) / 256, 256>>>(gkt_idx, Eg, 1);
    aggregate_kernel<<<(M + 7) / 8, 256>>>(out, M, 0);
}

// round 9
// speedup vs baseline: 1.1491x; 1.1491x over previous
#include <cuda_runtime.h>
#include <cuda_bf16.h>
#include <cstdint>

// Problem constants (fixed by the dataset)
#define NMAX   50000
#define EMAX   800000
#define OUT_D  128
#define DIN    256
#define NVS    256
#define NATT   16

// ---------------------------------------------------------------------------
// Device scratch
// ---------------------------------------------------------------------------
__device__ float    d_bvs[NVS];
__device__ float    d_batt[NATT];
__device__ float    d_atte[EMAX * 8];
__device__ float    d_vs[NMAX * NVS];
__device__ float    d_att[NMAX * NATT];
__device__ float    d_hidden1[NMAX * OUT_D];
__device__ int      d_deg[NMAX];
__device__ int      d_off[NMAX + 1];
__device__ int      d_cursor[NMAX];
__device__ int      d_csrcol[EMAX];
__device__ float    d_logits[EMAX * 8];
__device__ unsigned d_rowmax[NMAX * 8];

// split-bf16 operands for the tensor-core GEMMs
__device__ __nv_bfloat16 d_zhi[NMAX * DIN];
__device__ __nv_bfloat16 d_zlo[NMAX * DIN];
__device__ __nv_bfloat16 d_Wbhi[NVS * DIN];
__device__ __nv_bfloat16 d_Wblo[NVS * DIN];
__device__ __nv_bfloat16 d_Wathi[NATT * DIN];   // att weights, [n][k]
__device__ __nv_bfloat16 d_Watlo[NATT * DIN];

// ---------------------------------------------------------------------------
// Helpers
// ---------------------------------------------------------------------------
__device__ __forceinline__ uint32_t smem_u32(const void* p) {
    uint32_t a;
    asm("{ .reg .u64 t; cvta.to.shared.u64 t, %1; cvt.u32.u64 %0, t; }" : "=r"(a) : "l"(p));
    return a;
}

__device__ __forceinline__ void ldsm4(uint32_t* r, uint32_t addr) {
    asm volatile("ldmatrix.sync.aligned.m8n8.x4.shared.b16 {%0,%1,%2,%3}, [%4];"
                 : "=r"(r[0]), "=r"(r[1]), "=r"(r[2]), "=r"(r[3]) : "r"(addr));
}

__device__ __forceinline__ void mma16816(float* c, const uint32_t* a, uint32_t b0, uint32_t b1) {
    asm volatile("mma.sync.aligned.m16n8k16.row.col.f32.bf16.bf16.f32 "
                 "{%0,%1,%2,%3}, {%4,%5,%6,%7}, {%8,%9}, {%0,%1,%2,%3};"
                 : "+f"(c[0]), "+f"(c[1]), "+f"(c[2]), "+f"(c[3])
                 : "r"(a[0]), "r"(a[1]), "r"(a[2]), "r"(a[3]), "r"(b0), "r"(b1));
}

__device__ __forceinline__ void cpasync16(uint32_t dst, const void* src) {
    asm volatile("cp.async.cg.shared.global [%0], [%1], 16;" :: "r"(dst), "l"(src));
}

// packed f32x2 ops (PTX 8.6, sm_100+ base feature)
__device__ __forceinline__ void fma_f32x2(unsigned long long& acc,
                                          unsigned long long a, unsigned long long b) {
    asm("fma.rn.f32x2 %0, %1, %2, %0;" : "+l"(acc) : "l"(a), "l"(b));
}
__device__ __forceinline__ unsigned long long add_f32x2(unsigned long long a,
                                                        unsigned long long b) {
    unsigned long long r;
    asm("add.rn.f32x2 %0, %1, %2;" : "=l"(r) : "l"(a), "l"(b));
    return r;
}
__device__ __forceinline__ unsigned long long pack_f32x2(float lo, float hi) {
    unsigned long long r;
    asm("mov.b64 %0, {%1, %2};" : "=l"(r) : "f"(lo), "f"(hi));
    return r;
}
__device__ __forceinline__ void unpack_f32x2(float& lo, float& hi, unsigned long long v) {
    asm("mov.b64 {%0, %1}, %2;" : "=f"(lo), "=f"(hi) : "l"(v));
}

__device__ __forceinline__ unsigned fenc(float f) {
    unsigned u = __float_as_uint(f);
    return (u & 0x80000000u) ? ~u : (u | 0x80000000u);
}
__device__ __forceinline__ float fdec(unsigned u) {
    return (u & 0x80000000u) ? __uint_as_float(u & 0x7FFFFFFFu)
                             : __uint_as_float(~u);
}

// ---------------------------------------------------------------------------
// Weight prep
// ---------------------------------------------------------------------------
__global__ void pack_bias_kernel(const float* __restrict__ bm, const float* __restrict__ bsk,
                                 const float* __restrict__ ba1, const float* __restrict__ ba2) {
    int i = blockIdx.x * blockDim.x + threadIdx.x;
    if (i < NVS)  d_bvs[i]  = (i < 128) ? bm[i] : bsk[i - 128];
    if (i < NATT) d_batt[i] = (i < 8) ? ba1[i] : ba2[i - 8];
}

__global__ void pack_weights_bf16_kernel(const float* __restrict__ Wm,
                                         const float* __restrict__ Wsk,
                                         const float* __restrict__ Wa1,
                                         const float* __restrict__ Wa2) {
    int i = blockIdx.x * blockDim.x + threadIdx.x;     // i = n*256 + k
    if (i < NVS * DIN) {
        int n = i >> 8, k = i & 255;
        float w = (n < 128) ? Wm[k * 128 + n] : Wsk[k * 128 + (n - 128)];
        __nv_bfloat16 hi = __float2bfloat16(w);
        __nv_bfloat16 lo = __float2bfloat16(w - __bfloat162float(hi));
        d_Wbhi[i] = hi;
        d_Wblo[i] = lo;
    }
    if (i < NATT * DIN) {
        int n = i >> 8, k = i & 255;
        float w = (n < 8) ? Wa1[k * 8 + n] : Wa2[k * 8 + (n - 8)];
        __nv_bfloat16 hi = __float2bfloat16(w);
        __nv_bfloat16 lo = __float2bfloat16(w - __bfloat162float(hi));
        d_Wathi[i] = hi;
        d_Watlo[i] = lo;
    }
}

// Convert a 128-wide fp32 node array into half of z (hi/lo split).
__global__ void convert_half_kernel(const float* __restrict__ src, int M, int half_off) {
    int idx = blockIdx.x * blockDim.x + threadIdx.x;
    if (idx >= M * 32) return;
    int row = idx >> 5, c4 = (idx & 31) * 4;
    float4 v = *(const float4*)&src[(size_t)row * 128 + c4];
    __nv_bfloat16 h[4], l[4];
    float f[4] = {v.x, v.y, v.z, v.w};
#pragma unroll
    for (int j = 0; j < 4; j++) {
        h[j] = __float2bfloat16(f[j]);
        l[j] = __float2bfloat16(f[j] - __bfloat162float(h[j]));
    }
    size_t o = (size_t)row * 256 + half_off + c4;
    *(uint2*)&d_zhi[o] = *(uint2*)h;
    *(uint2*)&d_zlo[o] = *(uint2*)l;
}

// ---------------------------------------------------------------------------
// Tensor GEMM via mma.sync, producing d_vs + d_att (fused), unchanged.
// ---------------------------------------------------------------------------
#define SSTR 72
#define SROWB (SSTR * 2)
#define OFF_AHI 0
#define OFF_ALO (128 * SROWB)
#define OFF_BHI (2 * 128 * SROWB)
#define OFF_BLO (3 * 128 * SROWB)
#define OFF_WHI (4 * 128 * SROWB)
#define OFF_WLO (OFF_WHI + 16 * SROWB)
#define GEMM_SMEM (OFF_WLO + 16 * SROWB)

__global__ __launch_bounds__(256, 1)
void gemm_vs_mma_kernel(int M) {
    extern __shared__ char smem[];
    uint32_t sb = smem_u32(smem);
    int t = threadIdx.x, wid = t >> 5, lane = t & 31;
    int warp_m = wid & 1, warp_n = wid >> 1;
    int row0 = blockIdx.x * 128, col0 = blockIdx.y * 128;
    bool blk_att = (blockIdx.y == 0);
    bool do_att = blk_att && (warp_n < 2);

    float acc[4][4][4];
#pragma unroll
    for (int a = 0; a < 4; a++)
#pragma unroll
        for (int b = 0; b < 4; b++)
#pragma unroll
            for (int c = 0; c < 4; c++) acc[a][b][c] = 0.f;
    float acc_att[4][4];
#pragma unroll
    for (int a = 0; a < 4; a++)
#pragma unroll
        for (int c = 0; c < 4; c++) acc_att[a][c] = 0.f;

    int lrow = lane & 15;
    int lcol = (lane >> 4) * 8;

    for (int kc = 0; kc < 4; kc++) {
        if (kc) __syncthreads();
        int kbase = kc * 64;
#pragma unroll
        for (int i = 0; i < 4; i++) {
            int idx = t + i * 256;
            int r = idx >> 3, k8 = (idx & 7) * 8;
            int grow = row0 + r;
            uint4 ahi = make_uint4(0, 0, 0, 0), alo = ahi;
            if (grow < M) {
                ahi = *(const uint4*)&d_zhi[(size_t)grow * 256 + kbase + k8];
                alo = *(const uint4*)&d_zlo[(size_t)grow * 256 + kbase + k8];
            }
            *(uint4*)(smem + OFF_AHI + r * SROWB + k8 * 2) = ahi;
            *(uint4*)(smem + OFF_ALO + r * SROWB + k8 * 2) = alo;
            int n = col0 + r;
            *(uint4*)(smem + OFF_BHI + r * SROWB + k8 * 2) =
                *(const uint4*)&d_Wbhi[(size_t)n * 256 + kbase + k8];
            *(uint4*)(smem + OFF_BLO + r * SROWB + k8 * 2) =
                *(const uint4*)&d_Wblo[(size_t)n * 256 + kbase + k8];
        }
        if (blk_att) {
            int r = (t >> 3) & 15, k8 = (t & 7) * 8;
            const __nv_bfloat16* src = (t < 128) ? d_Wathi : d_Watlo;
            int off = (t < 128) ? OFF_WHI : OFF_WLO;
            *(uint4*)(smem + off + r * SROWB + k8 * 2) =
                *(const uint4*)&src[(size_t)r * 256 + kbase + k8];
        }
        __syncthreads();

#pragma unroll
        for (int ks = 0; ks < 4; ks++) {
            int kofs = (ks * 16 + lcol) * 2;
            uint32_t ahi[4][4], alo[4][4];
#pragma unroll
            for (int mi = 0; mi < 4; mi++) {
                uint32_t arow = (uint32_t)(warp_m * 64 + mi * 16 + lrow);
                ldsm4(ahi[mi], sb + OFF_AHI + arow * SROWB + kofs);
                ldsm4(alo[mi], sb + OFF_ALO + arow * SROWB + kofs);
            }
            uint32_t bhi[2][4], blo[2][4];
#pragma unroll
            for (int nj = 0; nj < 2; nj++) {
                uint32_t brow = (uint32_t)(warp_n * 32 + nj * 16 + lrow);
                ldsm4(bhi[nj], sb + OFF_BHI + brow * SROWB + kofs);
                ldsm4(blo[nj], sb + OFF_BLO + brow * SROWB + kofs);
            }
#pragma unroll
            for (int mi = 0; mi < 4; mi++) {
#pragma unroll
                for (int ni = 0; ni < 4; ni++) {
                    int nj = ni >> 1, pr = ni & 1;
                    uint32_t bh0 = bhi[nj][pr], bh1 = bhi[nj][pr + 2];
                    uint32_t bl0 = blo[nj][pr], bl1 = blo[nj][pr + 2];
                    mma16816(acc[mi][ni], ahi[mi], bh0, bh1);
                    mma16816(acc[mi][ni], ahi[mi], bl0, bl1);
                    mma16816(acc[mi][ni], alo[mi], bh0, bh1);
                }
            }
            if (do_att) {
                uint32_t whi[4], wlo[4];
                ldsm4(whi, sb + OFF_WHI + (uint32_t)lrow * SROWB + kofs);
                ldsm4(wlo, sb + OFF_WLO + (uint32_t)lrow * SROWB + kofs);
                uint32_t wh0 = whi[warp_n], wh1 = whi[warp_n + 2];
                uint32_t wl0 = wlo[warp_n], wl1 = wlo[warp_n + 2];
#pragma unroll
                for (int mi = 0; mi < 4; mi++) {
                    mma16816(acc_att[mi], ahi[mi], wh0, wh1);
                    mma16816(acc_att[mi], ahi[mi], wl0, wl1);
                    mma16816(acc_att[mi], alo[mi], wh0, wh1);
                }
            }
        }
    }

#pragma unroll
    for (int mi = 0; mi < 4; mi++) {
        int rA = row0 + warp_m * 64 + mi * 16 + (lane >> 2);
        int rB = rA + 8;
#pragma unroll
        for (int ni = 0; ni < 4; ni++) {
            int col = col0 + warp_n * 32 + ni * 8 + (lane & 3) * 2;
            float2 bias = *(const float2*)&d_bvs[col];
            if (rA < M) {
                float2 o = make_float2(acc[mi][ni][0] + bias.x, acc[mi][ni][1] + bias.y);
                *(float2*)&d_vs[(size_t)rA * 256 + col] = o;
            }
            if (rB < M) {
                float2 o = make_float2(acc[mi][ni][2] + bias.x, acc[mi][ni][3] + bias.y);
                *(float2*)&d_vs[(size_t)rB * 256 + col] = o;
            }
        }
        if (do_att) {
            int col = warp_n * 8 + (lane & 3) * 2;
            float2 bias = *(const float2*)&d_batt[col];
            if (rA < M) {
                float2 o = make_float2(acc_att[mi][0] + bias.x, acc_att[mi][1] + bias.y);
                *(float2*)&d_att[(size_t)rA * 16 + col] = o;
            }
            if (rB < M) {
                float2 o = make_float2(acc_att[mi][2] + bias.x, acc_att[mi][3] + bias.y);
                *(float2*)&d_att[(size_t)rB * 16 + col] = o;
            }
        }
    }
}

// ---------------------------------------------------------------------------
// Edge-feature attention: cp.async tile streamer (R7 structure) with packed
// f32x2 FMAs. Lane (h = lane&7, s = lane>>3) covers k in [s*32, s*32+32) for
// head h; SMEM reads are 8-way broadcast, conflict-free (seg stride 36 words).
// ---------------------------------------------------------------------------
#define EA_TILE 32
#define EA_ROWW 144

__global__ __launch_bounds__(256, 4)
void edge_att_kernel(const float* __restrict__ efts,
                     const float* __restrict__ Wae,
                     const float* __restrict__ bae, int E, int ntiles) {
    __shared__ float sbuf[2][EA_TILE * EA_ROWW];
    int t = threadIdx.x, lane = t & 31, w = t >> 5;
    int h = lane & 7, s = lane >> 3;

    // packed weight pairs: w64[j] = (Wae[(s*32+2j)*8+h], Wae[(s*32+2j+1)*8+h])
    unsigned long long w64[16];
#pragma unroll
    for (int j = 0; j < 16; j++)
        w64[j] = pack_f32x2(Wae[(s * 32 + 2 * j) * 8 + h],
                            Wae[(s * 32 + 2 * j + 1) * 8 + h]);
    float b = bae[h];

    uint32_t sb0 = smem_u32(&sbuf[0][0]);
    uint32_t sb1 = smem_u32(&sbuf[1][0]);

    int j = t & 31;
    int sseg = j >> 3, si = (j & 7) * 4;
    uint32_t dst_off = (uint32_t)((sseg * 36 + si) * 4);

    int ti = blockIdx.x;
    int tstep = gridDim.x;
    if (ti >= ntiles) return;

    {
        int ebase = ti * EA_TILE;
#pragma unroll
        for (int it = 0; it < 4; it++) {
            int r = it * 8 + w;
            int e = ebase + r; if (e >= E) e = E - 1;
            cpasync16(sb0 + (uint32_t)(r * EA_ROWW * 4) + dst_off,
                      efts + (size_t)e * 128 + j * 4);
        }
        asm volatile("cp.async.commit_group;" ::: "memory");
    }

    int bi = 0;
    for (; ti < ntiles; ti += tstep) {
        int tn = ti + tstep;
        if (tn < ntiles) {
            uint32_t sbn = (bi == 0) ? sb1 : sb0;
            int ebase = tn * EA_TILE;
#pragma unroll
            for (int it = 0; it < 4; it++) {
                int r = it * 8 + w;
                int e = ebase + r; if (e >= E) e = E - 1;
                cpasync16(sbn + (uint32_t)(r * EA_ROWW * 4) + dst_off,
                          efts + (size_t)e * 128 + j * 4);
            }
            asm volatile("cp.async.commit_group;" ::: "memory");
            asm volatile("cp.async.wait_group 1;" ::: "memory");
        } else {
            asm volatile("cp.async.wait_group 0;" ::: "memory");
        }
        __syncthreads();

        const float* buf = &sbuf[bi][0];
        int ebase = ti * EA_TILE;
#pragma unroll
        for (int q = 0; q < 4; q++) {
            int r = w * 4 + q;
            int e = ebase + r;
            const float* seg = buf + r * EA_ROWW + s * 36;
            unsigned long long a0 = 0ull, a1 = 0ull;   // (+0.0f, +0.0f) packed
#pragma unroll
            for (int i = 0; i < 8; i++) {
                ulonglong2 p = *(const ulonglong2*)(seg + i * 4);
                fma_f32x2(a0, p.x, w64[i * 2]);
                fma_f32x2(a1, p.y, w64[i * 2 + 1]);
            }
            unsigned long long asum = add_f32x2(a0, a1);
            float flo, fhi;
            unpack_f32x2(flo, fhi, asum);
            float acc = flo + fhi;
            acc += __shfl_xor_sync(0xffffffffu, acc, 8);
            acc += __shfl_xor_sync(0xffffffffu, acc, 16);
            if (lane < 8 && e < E) d_atte[(size_t)e * 8 + lane] = acc + b;
        }
        __syncthreads();
        bi ^= 1;
    }
}

// ---------------------------------------------------------------------------
// CSR build helpers
// ---------------------------------------------------------------------------
__global__ void zero_init_kernel(int M) {
    int i = blockIdx.x * blockDim.x + threadIdx.x;
    if (i < M) d_deg[i] = 0;
    if (i < M * 8) d_rowmax[i] = 0u;
}

__global__ void count_kernel(const int* __restrict__ idx, int E) {
    int e = blockIdx.x * blockDim.x + threadIdx.x;
    if (e >= E) return;
    int2 rc = ((const int2*)idx)[e];
    atomicAdd(&d_deg[rc.x], 1);
}

__global__ void scan_kernel(int n) {
    __shared__ int wsum[32];
    __shared__ int tot_s;
    int t = threadIdx.x, lane = t & 31, wid = t >> 5;
    int carry = 0;
    for (int base = 0; base < n; base += 1024) {
        int i = base + t;
        int x = (i < n) ? d_deg[i] : 0;
        int v = x;
#pragma unroll
        for (int d = 1; d < 32; d <<= 1) {
            int u = __shfl_up_sync(0xffffffffu, v, d);
            if (lane >= d) v += u;
        }
        if (lane == 31) wsum[wid] = v;
        __syncthreads();
        if (wid == 0) {
            int s = wsum[lane];
            int sv = s;
#pragma unroll
            for (int d = 1; d < 32; d <<= 1) {
                int u = __shfl_up_sync(0xffffffffu, sv, d);
                if (lane >= d) sv += u;
            }
            wsum[lane] = sv - s;
            if (lane == 31) tot_s = sv;
        }
        __syncthreads();
        int excl = carry + wsum[wid] + (v - x);
        if (i < n) { d_off[i] = excl; d_cursor[i] = excl; }
        carry += tot_s;
        __syncthreads();
    }
    if (t == 0) d_off[n] = carry;
}

// ---------------------------------------------------------------------------
// Scatter + logits
// ---------------------------------------------------------------------------
__global__ void scatter_logits_kernel(const int* __restrict__ idx, int E, int use_atte) {
    int e = blockIdx.x * blockDim.x + threadIdx.x;
    if (e >= E) return;
    int2 rc = ((const int2*)idx)[e];
    int row = rc.x, col = rc.y;
    int pos = atomicAdd(&d_cursor[row], 1);
    d_csrcol[pos] = col;
    const float4* pa = (const float4*)&d_att[(size_t)row * 16];
    const float4* pb = (const float4*)&d_att[(size_t)col * 16 + 8];
    float4 a0 = pa[0], a1 = pa[1];
    float4 b0 = pb[0], b1 = pb[1];
    float lg[8] = {a0.x + b0.x, a0.y + b0.y, a0.z + b0.z, a0.w + b0.w,
                   a1.x + b1.x, a1.y + b1.y, a1.z + b1.z, a1.w + b1.w};
    if (use_atte) {
        const float4* pe = (const float4*)&d_atte[(size_t)e * 8];
        float4 e0 = pe[0], e1 = pe[1];
        lg[0] += e0.x; lg[1] += e0.y; lg[2] += e0.z; lg[3] += e0.w;
        lg[4] += e1.x; lg[5] += e1.y; lg[6] += e1.z; lg[7] += e1.w;
    }
#pragma unroll
    for (int h = 0; h < 8; h++) {
        float u = lg[h];
        u = (u > 0.f) ? u : 0.01f * u;
        lg[h] = u;
        atomicMax(&d_rowmax[(size_t)row * 8 + h], fenc(u));
    }
    *(float4*)&d_logits[(size_t)pos * 8]     = make_float4(lg[0], lg[1], lg[2], lg[3]);
    *(float4*)&d_logits[(size_t)pos * 8 + 4] = make_float4(lg[4], lg[5], lg[6], lg[7]);
}

// ---------------------------------------------------------------------------
// Aggregate: warp per row; optionally writes bf16 hi/lo z-half (pass 1).
// ---------------------------------------------------------------------------
__global__ __launch_bounds__(256)
void aggregate_kernel(float* __restrict__ outp, int M, int write_z) {
    int warp = (blockIdx.x * blockDim.x + threadIdx.x) >> 5;
    if (warp >= M) return;
    int lane = threadIdx.x & 31;
    int c0 = lane * 4;
    int h = lane >> 2;
    float mx = fdec(d_rowmax[(size_t)warp * 8 + h]);
    int p = d_off[warp], pend = d_off[warp + 1];
    float s = 0.f;
    float4 acc = make_float4(0.f, 0.f, 0.f, 0.f);
    for (; p < pend; ++p) {
        int col = d_csrcol[p];
        float w = __expf(d_logits[(size_t)p * 8 + h] - mx);
        float4 v = *(const float4*)&d_vs[(size_t)col * 256 + c0];
        s += w;
        acc.x += w * v.x; acc.y += w * v.y; acc.z += w * v.z; acc.w += w * v.w;
    }
    float4 sk = *(const float4*)&d_vs[(size_t)warp * 256 + 128 + c0];
    float inv = (s > 0.f) ? (1.f / s) : 0.f;
    float4 o;
    o.x = fmaxf(acc.x * inv + sk.x, 0.f);
    o.y = fmaxf(acc.y * inv + sk.y, 0.f);
    o.z = fmaxf(acc.z * inv + sk.z, 0.f);
    o.w = fmaxf(acc.w * inv + sk.w, 0.f);
    *(float4*)&outp[(size_t)warp * 128 + c0] = o;
    if (write_z) {
        float f[4] = {o.x, o.y, o.z, o.w};
        __nv_bfloat16 hh[4], ll[4];
#pragma unroll
        for (int jj = 0; jj < 4; jj++) {
            hh[jj] = __float2bfloat16(f[jj]);
            ll[jj] = __float2bfloat16(f[jj] - __bfloat162float(hh[jj]));
        }
        size_t zo = (size_t)warp * 256 + 128 + c0;
        *(uint2*)&d_zhi[zo] = *(uint2*)hh;
        *(uint2*)&d_zlo[zo] = *(uint2*)ll;
    }
}

// ---------------------------------------------------------------------------
// Launch
// ---------------------------------------------------------------------------
extern "C" void kernel_launch(void* const* d_in, const int* in_sizes, int n_in,
                              void* d_out, int out_size) {
    const float* node_fts = (const float*)d_in[0];
    const float* gkt_efts = (const float*)d_in[1];
    const float* hidden   = (const float*)d_in[2];
    const int*   cfg_idx  = (const int*)d_in[3];
    const int*   gkt_idx  = (const int*)d_in[4];
    const float* W_m    = (const float*)d_in[5];
    const float* b_m    = (const float*)d_in[6];
    const float* W_skip = (const float*)d_in[7];
    const float* b_skip = (const float*)d_in[8];
    const float* W_a1   = (const float*)d_in[9];
    const float* b_a1   = (const float*)d_in[10];
    const float* W_a2   = (const float*)d_in[11];
    const float* b_a2   = (const float*)d_in[12];
    const float* W_ae   = (const float*)d_in[13];
    const float* b_ae   = (const float*)d_in[14];
    float* out = (float*)d_out;

    int M  = in_sizes[0] / 128;
    int Ec = in_sizes[3] / 2;
    int Eg = in_sizes[4] / 2;

    float* hid1 = nullptr;
    cudaGetSymbolAddress((void**)&hid1, d_hidden1);

    cudaFuncSetAttribute(gemm_vs_mma_kernel,
                         cudaFuncAttributeMaxDynamicSharedMemorySize, GEMM_SMEM);

    pack_bias_kernel<<<1, 256>>>(b_m, b_skip, b_a1, b_a2);
    pack_weights_bf16_kernel<<<(NVS * DIN + 255) / 256, 256>>>(W_m, W_skip, W_a1, W_a2);
    convert_half_kernel<<<(M * 32 + 255) / 256, 256>>>(node_fts, M, 0);
    {
        int ntiles = (Eg + EA_TILE - 1) / EA_TILE;
        edge_att_kernel<<<1776, 256>>>(gkt_efts, W_ae, b_ae, Eg, ntiles);
    }

    dim3 ggrid((M + 127) / 128, 2);

    // ---- pass 1 (cfg) ----
    convert_half_kernel<<<(M * 32 + 255) / 256, 256>>>(hidden, M, 128);
    gemm_vs_mma_kernel<<<ggrid, 256, GEMM_SMEM>>>(M);    // vs + att fused
    zero_init_kernel<<<(M * 8 + 255) / 256, 256>>>(M);
    count_kernel<<<(Ec + 255) / 256, 256>>>(cfg_idx, Ec);
    scan_kernel<<<1, 1024>>>(M);
    scatter_logits_kernel<<<(Ec + 255) / 256, 256>>>(cfg_idx, Ec, 0);
    aggregate_kernel<<<(M + 7) / 8, 256>>>(hid1, M, 1);

    // ---- pass 2 (gkt) ----
    gemm_vs_mma_kernel<<<ggrid, 256, GEMM_SMEM>>>(M);    // vs + att fused
    zero_init_kernel<<<(M * 8 + 255) / 256, 256>>>(M);
    count_kernel<<<(Eg + 255) / 256, 256>>>(gkt_idx, Eg);
    scan_kernel<<<1, 1024>>>(M);
    scatter_logits_kernel<<<(Eg + 255) / 256, 256>>>(gkt_idx, Eg, 1);
    aggregate_kernel<<<(M + 7) / 8, 256>>>(out, M, 0);
}

// round 10
// speedup vs baseline: 1.2805x; 1.1144x over previous
#include <cuda_runtime.h>
#include <cuda_bf16.h>
#include <cstdint>

// Problem constants (fixed by the dataset)
#define NMAX   50000
#define EMAX   800000
#define OUT_D  128
#define DIN    256
#define NVS    256
#define NATT   16

// ---------------------------------------------------------------------------
// Device scratch
// ---------------------------------------------------------------------------
__device__ float    d_bvs[NVS];
__device__ float    d_batt[NATT];
__device__ float    d_atte[EMAX * 8];
__device__ float    d_vs[NMAX * NVS];
__device__ float    d_att[NMAX * NATT];
__device__ float    d_hidden1[NMAX * OUT_D];
__device__ int      d_deg[NMAX];
__device__ int      d_off[NMAX + 1];
__device__ int      d_cursor[NMAX];
__device__ int      d_csrcol[EMAX];
__device__ float    d_eweights[EMAX * 8];    // exp(leaky_relu(logit)) per (edge,head)

// split-bf16 operands for the tensor-core GEMMs
__device__ __nv_bfloat16 d_zhi[NMAX * DIN];
__device__ __nv_bfloat16 d_zlo[NMAX * DIN];
__device__ __nv_bfloat16 d_Wbhi[NVS * DIN];
__device__ __nv_bfloat16 d_Wblo[NVS * DIN];
__device__ __nv_bfloat16 d_Wathi[NATT * DIN];   // att weights, [n][k]
__device__ __nv_bfloat16 d_Watlo[NATT * DIN];

// ---------------------------------------------------------------------------
// Helpers
// ---------------------------------------------------------------------------
__device__ __forceinline__ uint32_t smem_u32(const void* p) {
    uint32_t a;
    asm("{ .reg .u64 t; cvta.to.shared.u64 t, %1; cvt.u32.u64 %0, t; }" : "=r"(a) : "l"(p));
    return a;
}

__device__ __forceinline__ void ldsm4(uint32_t* r, uint32_t addr) {
    asm volatile("ldmatrix.sync.aligned.m8n8.x4.shared.b16 {%0,%1,%2,%3}, [%4];"
                 : "=r"(r[0]), "=r"(r[1]), "=r"(r[2]), "=r"(r[3]) : "r"(addr));
}

__device__ __forceinline__ void mma16816(float* c, const uint32_t* a, uint32_t b0, uint32_t b1) {
    asm volatile("mma.sync.aligned.m16n8k16.row.col.f32.bf16.bf16.f32 "
                 "{%0,%1,%2,%3}, {%4,%5,%6,%7}, {%8,%9}, {%0,%1,%2,%3};"
                 : "+f"(c[0]), "+f"(c[1]), "+f"(c[2]), "+f"(c[3])
                 : "r"(a[0]), "r"(a[1]), "r"(a[2]), "r"(a[3]), "r"(b0), "r"(b1));
}

__device__ __forceinline__ void cpasync16(uint32_t dst, const void* src) {
    asm volatile("cp.async.cg.shared.global [%0], [%1], 16;" :: "r"(dst), "l"(src));
}

// packed f32x2 ops (PTX 8.6, sm_100+ base feature)
__device__ __forceinline__ void fma_f32x2(unsigned long long& acc,
                                          unsigned long long a, unsigned long long b) {
    asm("fma.rn.f32x2 %0, %1, %2, %0;" : "+l"(acc) : "l"(a), "l"(b));
}
__device__ __forceinline__ unsigned long long add_f32x2(unsigned long long a,
                                                        unsigned long long b) {
    unsigned long long r;
    asm("add.rn.f32x2 %0, %1, %2;" : "=l"(r) : "l"(a), "l"(b));
    return r;
}
__device__ __forceinline__ unsigned long long pack_f32x2(float lo, float hi) {
    unsigned long long r;
    asm("mov.b64 %0, {%1, %2};" : "=l"(r) : "f"(lo), "f"(hi));
    return r;
}
__device__ __forceinline__ void unpack_f32x2(float& lo, float& hi, unsigned long long v) {
    asm("mov.b64 {%0, %1}, %2;" : "=f"(lo), "=f"(hi) : "l"(v));
}

// ---------------------------------------------------------------------------
// Weight prep
// ---------------------------------------------------------------------------
__global__ void pack_bias_kernel(const float* __restrict__ bm, const float* __restrict__ bsk,
                                 const float* __restrict__ ba1, const float* __restrict__ ba2) {
    int i = blockIdx.x * blockDim.x + threadIdx.x;
    if (i < NVS)  d_bvs[i]  = (i < 128) ? bm[i] : bsk[i - 128];
    if (i < NATT) d_batt[i] = (i < 8) ? ba1[i] : ba2[i - 8];
}

__global__ void pack_weights_bf16_kernel(const float* __restrict__ Wm,
                                         const float* __restrict__ Wsk,
                                         const float* __restrict__ Wa1,
                                         const float* __restrict__ Wa2) {
    int i = blockIdx.x * blockDim.x + threadIdx.x;     // i = n*256 + k
    if (i < NVS * DIN) {
        int n = i >> 8, k = i & 255;
        float w = (n < 128) ? Wm[k * 128 + n] : Wsk[k * 128 + (n - 128)];
        __nv_bfloat16 hi = __float2bfloat16(w);
        __nv_bfloat16 lo = __float2bfloat16(w - __bfloat162float(hi));
        d_Wbhi[i] = hi;
        d_Wblo[i] = lo;
    }
    if (i < NATT * DIN) {
        int n = i >> 8, k = i & 255;
        float w = (n < 8) ? Wa1[k * 8 + n] : Wa2[k * 8 + (n - 8)];
        __nv_bfloat16 hi = __float2bfloat16(w);
        __nv_bfloat16 lo = __float2bfloat16(w - __bfloat162float(hi));
        d_Wathi[i] = hi;
        d_Watlo[i] = lo;
    }
}

// Convert a 128-wide fp32 node array into half of z (hi/lo split).
__global__ void convert_half_kernel(const float* __restrict__ src, int M, int half_off) {
    int idx = blockIdx.x * blockDim.x + threadIdx.x;
    if (idx >= M * 32) return;
    int row = idx >> 5, c4 = (idx & 31) * 4;
    float4 v = *(const float4*)&src[(size_t)row * 128 + c4];
    __nv_bfloat16 h[4], l[4];
    float f[4] = {v.x, v.y, v.z, v.w};
#pragma unroll
    for (int j = 0; j < 4; j++) {
        h[j] = __float2bfloat16(f[j]);
        l[j] = __float2bfloat16(f[j] - __bfloat162float(h[j]));
    }
    size_t o = (size_t)row * 256 + half_off + c4;
    *(uint2*)&d_zhi[o] = *(uint2*)h;
    *(uint2*)&d_zlo[o] = *(uint2*)l;
}

// ---------------------------------------------------------------------------
// Tensor GEMM via mma.sync, producing d_vs + d_att (fused), unchanged.
// ---------------------------------------------------------------------------
#define SSTR 72
#define SROWB (SSTR * 2)
#define OFF_AHI 0
#define OFF_ALO (128 * SROWB)
#define OFF_BHI (2 * 128 * SROWB)
#define OFF_BLO (3 * 128 * SROWB)
#define OFF_WHI (4 * 128 * SROWB)
#define OFF_WLO (OFF_WHI + 16 * SROWB)
#define GEMM_SMEM (OFF_WLO + 16 * SROWB)

__global__ __launch_bounds__(256, 1)
void gemm_vs_mma_kernel(int M) {
    extern __shared__ char smem[];
    uint32_t sb = smem_u32(smem);
    int t = threadIdx.x, wid = t >> 5, lane = t & 31;
    int warp_m = wid & 1, warp_n = wid >> 1;
    int row0 = blockIdx.x * 128, col0 = blockIdx.y * 128;
    bool blk_att = (blockIdx.y == 0);
    bool do_att = blk_att && (warp_n < 2);

    float acc[4][4][4];
#pragma unroll
    for (int a = 0; a < 4; a++)
#pragma unroll
        for (int b = 0; b < 4; b++)
#pragma unroll
            for (int c = 0; c < 4; c++) acc[a][b][c] = 0.f;
    float acc_att[4][4];
#pragma unroll
    for (int a = 0; a < 4; a++)
#pragma unroll
        for (int c = 0; c < 4; c++) acc_att[a][c] = 0.f;

    int lrow = lane & 15;
    int lcol = (lane >> 4) * 8;

    for (int kc = 0; kc < 4; kc++) {
        if (kc) __syncthreads();
        int kbase = kc * 64;
#pragma unroll
        for (int i = 0; i < 4; i++) {
            int idx = t + i * 256;
            int r = idx >> 3, k8 = (idx & 7) * 8;
            int grow = row0 + r;
            uint4 ahi = make_uint4(0, 0, 0, 0), alo = ahi;
            if (grow < M) {
                ahi = *(const uint4*)&d_zhi[(size_t)grow * 256 + kbase + k8];
                alo = *(const uint4*)&d_zlo[(size_t)grow * 256 + kbase + k8];
            }
            *(uint4*)(smem + OFF_AHI + r * SROWB + k8 * 2) = ahi;
            *(uint4*)(smem + OFF_ALO + r * SROWB + k8 * 2) = alo;
            int n = col0 + r;
            *(uint4*)(smem + OFF_BHI + r * SROWB + k8 * 2) =
                *(const uint4*)&d_Wbhi[(size_t)n * 256 + kbase + k8];
            *(uint4*)(smem + OFF_BLO + r * SROWB + k8 * 2) =
                *(const uint4*)&d_Wblo[(size_t)n * 256 + kbase + k8];
        }
        if (blk_att) {
            int r = (t >> 3) & 15, k8 = (t & 7) * 8;
            const __nv_bfloat16* src = (t < 128) ? d_Wathi : d_Watlo;
            int off = (t < 128) ? OFF_WHI : OFF_WLO;
            *(uint4*)(smem + off + r * SROWB + k8 * 2) =
                *(const uint4*)&src[(size_t)r * 256 + kbase + k8];
        }
        __syncthreads();

#pragma unroll
        for (int ks = 0; ks < 4; ks++) {
            int kofs = (ks * 16 + lcol) * 2;
            uint32_t ahi[4][4], alo[4][4];
#pragma unroll
            for (int mi = 0; mi < 4; mi++) {
                uint32_t arow = (uint32_t)(warp_m * 64 + mi * 16 + lrow);
                ldsm4(ahi[mi], sb + OFF_AHI + arow * SROWB + kofs);
                ldsm4(alo[mi], sb + OFF_ALO + arow * SROWB + kofs);
            }
            uint32_t bhi[2][4], blo[2][4];
#pragma unroll
            for (int nj = 0; nj < 2; nj++) {
                uint32_t brow = (uint32_t)(warp_n * 32 + nj * 16 + lrow);
                ldsm4(bhi[nj], sb + OFF_BHI + brow * SROWB + kofs);
                ldsm4(blo[nj], sb + OFF_BLO + brow * SROWB + kofs);
            }
#pragma unroll
            for (int mi = 0; mi < 4; mi++) {
#pragma unroll
                for (int ni = 0; ni < 4; ni++) {
                    int nj = ni >> 1, pr = ni & 1;
                    uint32_t bh0 = bhi[nj][pr], bh1 = bhi[nj][pr + 2];
                    uint32_t bl0 = blo[nj][pr], bl1 = blo[nj][pr + 2];
                    mma16816(acc[mi][ni], ahi[mi], bh0, bh1);
                    mma16816(acc[mi][ni], ahi[mi], bl0, bl1);
                    mma16816(acc[mi][ni], alo[mi], bh0, bh1);
                }
            }
            if (do_att) {
                uint32_t whi[4], wlo[4];
                ldsm4(whi, sb + OFF_WHI + (uint32_t)lrow * SROWB + kofs);
                ldsm4(wlo, sb + OFF_WLO + (uint32_t)lrow * SROWB + kofs);
                uint32_t wh0 = whi[warp_n], wh1 = whi[warp_n + 2];
                uint32_t wl0 = wlo[warp_n], wl1 = wlo[warp_n + 2];
#pragma unroll
                for (int mi = 0; mi < 4; mi++) {
                    mma16816(acc_att[mi], ahi[mi], wh0, wh1);
                    mma16816(acc_att[mi], ahi[mi], wl0, wl1);
                    mma16816(acc_att[mi], alo[mi], wh0, wh1);
                }
            }
        }
    }

#pragma unroll
    for (int mi = 0; mi < 4; mi++) {
        int rA = row0 + warp_m * 64 + mi * 16 + (lane >> 2);
        int rB = rA + 8;
#pragma unroll
        for (int ni = 0; ni < 4; ni++) {
            int col = col0 + warp_n * 32 + ni * 8 + (lane & 3) * 2;
            float2 bias = *(const float2*)&d_bvs[col];
            if (rA < M) {
                float2 o = make_float2(acc[mi][ni][0] + bias.x, acc[mi][ni][1] + bias.y);
                *(float2*)&d_vs[(size_t)rA * 256 + col] = o;
            }
            if (rB < M) {
                float2 o = make_float2(acc[mi][ni][2] + bias.x, acc[mi][ni][3] + bias.y);
                *(float2*)&d_vs[(size_t)rB * 256 + col] = o;
            }
        }
        if (do_att) {
            int col = warp_n * 8 + (lane & 3) * 2;
            float2 bias = *(const float2*)&d_batt[col];
            if (rA < M) {
                float2 o = make_float2(acc_att[mi][0] + bias.x, acc_att[mi][1] + bias.y);
                *(float2*)&d_att[(size_t)rA * 16 + col] = o;
            }
            if (rB < M) {
                float2 o = make_float2(acc_att[mi][2] + bias.x, acc_att[mi][3] + bias.y);
                *(float2*)&d_att[(size_t)rB * 16 + col] = o;
            }
        }
    }
}

// ---------------------------------------------------------------------------
// Edge-feature attention: cp.async tile streamer with packed f32x2 FMAs.
// ---------------------------------------------------------------------------
#define EA_TILE 32
#define EA_ROWW 144

__global__ __launch_bounds__(256, 4)
void edge_att_kernel(const float* __restrict__ efts,
                     const float* __restrict__ Wae,
                     const float* __restrict__ bae, int E, int ntiles) {
    __shared__ float sbuf[2][EA_TILE * EA_ROWW];
    int t = threadIdx.x, lane = t & 31, w = t >> 5;
    int h = lane & 7, s = lane >> 3;

    unsigned long long w64[16];
#pragma unroll
    for (int j = 0; j < 16; j++)
        w64[j] = pack_f32x2(Wae[(s * 32 + 2 * j) * 8 + h],
                            Wae[(s * 32 + 2 * j + 1) * 8 + h]);
    float b = bae[h];

    uint32_t sb0 = smem_u32(&sbuf[0][0]);
    uint32_t sb1 = smem_u32(&sbuf[1][0]);

    int j = t & 31;
    int sseg = j >> 3, si = (j & 7) * 4;
    uint32_t dst_off = (uint32_t)((sseg * 36 + si) * 4);

    int ti = blockIdx.x;
    int tstep = gridDim.x;
    if (ti >= ntiles) return;

    {
        int ebase = ti * EA_TILE;
#pragma unroll
        for (int it = 0; it < 4; it++) {
            int r = it * 8 + w;
            int e = ebase + r; if (e >= E) e = E - 1;
            cpasync16(sb0 + (uint32_t)(r * EA_ROWW * 4) + dst_off,
                      efts + (size_t)e * 128 + j * 4);
        }
        asm volatile("cp.async.commit_group;" ::: "memory");
    }

    int bi = 0;
    for (; ti < ntiles; ti += tstep) {
        int tn = ti + tstep;
        if (tn < ntiles) {
            uint32_t sbn = (bi == 0) ? sb1 : sb0;
            int ebase = tn * EA_TILE;
#pragma unroll
            for (int it = 0; it < 4; it++) {
                int r = it * 8 + w;
                int e = ebase + r; if (e >= E) e = E - 1;
                cpasync16(sbn + (uint32_t)(r * EA_ROWW * 4) + dst_off,
                          efts + (size_t)e * 128 + j * 4);
            }
            asm volatile("cp.async.commit_group;" ::: "memory");
            asm volatile("cp.async.wait_group 1;" ::: "memory");
        } else {
            asm volatile("cp.async.wait_group 0;" ::: "memory");
        }
        __syncthreads();

        const float* buf = &sbuf[bi][0];
        int ebase = ti * EA_TILE;
#pragma unroll
        for (int q = 0; q < 4; q++) {
            int r = w * 4 + q;
            int e = ebase + r;
            const float* seg = buf + r * EA_ROWW + s * 36;
            unsigned long long a0 = 0ull, a1 = 0ull;
#pragma unroll
            for (int i = 0; i < 8; i++) {
                ulonglong2 p = *(const ulonglong2*)(seg + i * 4);
                fma_f32x2(a0, p.x, w64[i * 2]);
                fma_f32x2(a1, p.y, w64[i * 2 + 1]);
            }
            unsigned long long asum = add_f32x2(a0, a1);
            float flo, fhi;
            unpack_f32x2(flo, fhi, asum);
            float acc = flo + fhi;
            acc += __shfl_xor_sync(0xffffffffu, acc, 8);
            acc += __shfl_xor_sync(0xffffffffu, acc, 16);
            if (lane < 8 && e < E) d_atte[(size_t)e * 8 + lane] = acc + b;
        }
        __syncthreads();
        bi ^= 1;
    }
}

// ---------------------------------------------------------------------------
// CSR build helpers
// ---------------------------------------------------------------------------
__global__ void count_kernel(const int* __restrict__ idx, int E) {
    int e = blockIdx.x * blockDim.x + threadIdx.x;
    if (e >= E) return;
    int2 rc = ((const int2*)idx)[e];
    atomicAdd(&d_deg[rc.x], 1);
}

__global__ void scan_kernel(int n) {
    __shared__ int wsum[32];
    __shared__ int tot_s;
    int t = threadIdx.x, lane = t & 31, wid = t >> 5;
    int carry = 0;
    for (int base = 0; base < n; base += 1024) {
        int i = base + t;
        int x = (i < n) ? d_deg[i] : 0;
        int v = x;
#pragma unroll
        for (int d = 1; d < 32; d <<= 1) {
            int u = __shfl_up_sync(0xffffffffu, v, d);
            if (lane >= d) v += u;
        }
        if (lane == 31) wsum[wid] = v;
        __syncthreads();
        if (wid == 0) {
            int s = wsum[lane];
            int sv = s;
#pragma unroll
            for (int d = 1; d < 32; d <<= 1) {
                int u = __shfl_up_sync(0xffffffffu, sv, d);
                if (lane >= d) sv += u;
            }
            wsum[lane] = sv - s;
            if (lane == 31) tot_s = sv;
        }
        __syncthreads();
        int excl = carry + wsum[wid] + (v - x);
        if (i < n) { d_off[i] = excl; d_cursor[i] = excl; }
        carry += tot_s;
        __syncthreads();
    }
    if (t == 0) d_off[n] = carry;
}

// ---------------------------------------------------------------------------
// Scatter: compute exp(leaky_relu(logits)) and place at CSR position.
// No rowmax (logits bounded ~10; exp safe in fp32), exp done HERE once.
// ---------------------------------------------------------------------------
__global__ void scatter_logits_kernel(const int* __restrict__ idx, int E, int use_atte) {
    int e = blockIdx.x * blockDim.x + threadIdx.x;
    if (e >= E) return;
    int2 rc = ((const int2*)idx)[e];
    int row = rc.x, col = rc.y;
    int pos = atomicAdd(&d_cursor[row], 1);
    d_csrcol[pos] = col;
    const float4* pa = (const float4*)&d_att[(size_t)row * 16];
    const float4* pb = (const float4*)&d_att[(size_t)col * 16 + 8];
    float4 a0 = pa[0], a1 = pa[1];
    float4 b0 = pb[0], b1 = pb[1];
    float lg[8] = {a0.x + b0.x, a0.y + b0.y, a0.z + b0.z, a0.w + b0.w,
                   a1.x + b1.x, a1.y + b1.y, a1.z + b1.z, a1.w + b1.w};
    if (use_atte) {
        const float4* pe = (const float4*)&d_atte[(size_t)e * 8];
        float4 e0 = pe[0], e1 = pe[1];
        lg[0] += e0.x; lg[1] += e0.y; lg[2] += e0.z; lg[3] += e0.w;
        lg[4] += e1.x; lg[5] += e1.y; lg[6] += e1.z; lg[7] += e1.w;
    }
#pragma unroll
    for (int h = 0; h < 8; h++) {
        float u = lg[h];
        u = (u > 0.f) ? u : 0.01f * u;
        lg[h] = __expf(u);
    }
    *(float4*)&d_eweights[(size_t)pos * 8]     = make_float4(lg[0], lg[1], lg[2], lg[3]);
    *(float4*)&d_eweights[(size_t)pos * 8 + 4] = make_float4(lg[4], lg[5], lg[6], lg[7]);
}

// ---------------------------------------------------------------------------
// Aggregate: warp per row. Weights are precomputed exp values.
// ---------------------------------------------------------------------------
__global__ __launch_bounds__(256)
void aggregate_kernel(float* __restrict__ outp, int M, int write_z) {
    int warp = (blockIdx.x * blockDim.x + threadIdx.x) >> 5;
    if (warp >= M) return;
    int lane = threadIdx.x & 31;
    int c0 = lane * 4;
    int h = lane >> 2;
    int p = d_off[warp], pend = d_off[warp + 1];
    float s = 0.f;
    float4 acc = make_float4(0.f, 0.f, 0.f, 0.f);
    for (; p < pend; ++p) {
        int col = d_csrcol[p];
        float w = d_eweights[(size_t)p * 8 + h];
        float4 v = *(const float4*)&d_vs[(size_t)col * 256 + c0];
        s += w;
        acc.x += w * v.x; acc.y += w * v.y; acc.z += w * v.z; acc.w += w * v.w;
    }
    float4 sk = *(const float4*)&d_vs[(size_t)warp * 256 + 128 + c0];
    float inv = (s > 0.f) ? (1.f / s) : 0.f;
    float4 o;
    o.x = fmaxf(acc.x * inv + sk.x, 0.f);
    o.y = fmaxf(acc.y * inv + sk.y, 0.f);
    o.z = fmaxf(acc.z * inv + sk.z, 0.f);
    o.w = fmaxf(acc.w * inv + sk.w, 0.f);
    *(float4*)&outp[(size_t)warp * 128 + c0] = o;
    if (write_z) {
        float f[4] = {o.x, o.y, o.z, o.w};
        __nv_bfloat16 hh[4], ll[4];
#pragma unroll
        for (int jj = 0; jj < 4; jj++) {
            hh[jj] = __float2bfloat16(f[jj]);
            ll[jj] = __float2bfloat16(f[jj] - __bfloat162float(hh[jj]));
        }
        size_t zo = (size_t)warp * 256 + 128 + c0;
        *(uint2*)&d_zhi[zo] = *(uint2*)hh;
        *(uint2*)&d_zlo[zo] = *(uint2*)ll;
    }
}

// ---------------------------------------------------------------------------
// Launch
// ---------------------------------------------------------------------------
extern "C" void kernel_launch(void* const* d_in, const int* in_sizes, int n_in,
                              void* d_out, int out_size) {
    const float* node_fts = (const float*)d_in[0];
    const float* gkt_efts = (const float*)d_in[1];
    const float* hidden   = (const float*)d_in[2];
    const int*   cfg_idx  = (const int*)d_in[3];
    const int*   gkt_idx  = (const int*)d_in[4];
    const float* W_m    = (const float*)d_in[5];
    const float* b_m    = (const float*)d_in[6];
    const float* W_skip = (const float*)d_in[7];
    const float* b_skip = (const float*)d_in[8];
    const float* W_a1   = (const float*)d_in[9];
    const float* b_a1   = (const float*)d_in[10];
    const float* W_a2   = (const float*)d_in[11];
    const float* b_a2   = (const float*)d_in[12];
    const float* W_ae   = (const float*)d_in[13];
    const float* b_ae   = (const float*)d_in[14];
    float* out = (float*)d_out;

    int M  = in_sizes[0] / 128;
    int Ec = in_sizes[3] / 2;
    int Eg = in_sizes[4] / 2;

    float* hid1 = nullptr;
    cudaGetSymbolAddress((void**)&hid1, d_hidden1);
    int* degp = nullptr;
    cudaGetSymbolAddress((void**)&degp, d_deg);

    cudaFuncSetAttribute(gemm_vs_mma_kernel,
                         cudaFuncAttributeMaxDynamicSharedMemorySize, GEMM_SMEM);

    pack_bias_kernel<<<1, 256>>>(b_m, b_skip, b_a1, b_a2);
    pack_weights_bf16_kernel<<<(NVS * DIN + 255) / 256, 256>>>(W_m, W_skip, W_a1, W_a2);
    convert_half_kernel<<<(M * 32 + 255) / 256, 256>>>(node_fts, M, 0);
    {
        int ntiles = (Eg + EA_TILE - 1) / EA_TILE;
        edge_att_kernel<<<1776, 256>>>(gkt_efts, W_ae, b_ae, Eg, ntiles);
    }

    dim3 ggrid((M + 127) / 128, 2);

    // ---- pass 1 (cfg) ----
    convert_half_kernel<<<(M * 32 + 255) / 256, 256>>>(hidden, M, 128);
    gemm_vs_mma_kernel<<<ggrid, 256, GEMM_SMEM>>>(M);    // vs + att fused
    cudaMemsetAsync(degp, 0, (size_t)M * sizeof(int));
    count_kernel<<<(Ec + 255) / 256, 256>>>(cfg_idx, Ec);
    scan_kernel<<<1, 1024>>>(M);
    scatter_logits_kernel<<<(Ec + 255) / 256, 256>>>(cfg_idx, Ec, 0);
    aggregate_kernel<<<(M + 7) / 8, 256>>>(hid1, M, 1);

    // ---- pass 2 (gkt) ----
    gemm_vs_mma_kernel<<<ggrid, 256, GEMM_SMEM>>>(M);    // vs + att fused
    cudaMemsetAsync(degp, 0, (size_t)M * sizeof(int));
    count_kernel<<<(Eg + 255) / 256, 256>>>(gkt_idx, Eg);
    scan_kernel<<<1, 1024>>>(M);
    scatter_logits_kernel<<<(Eg + 255) / 256, 256>>>(gkt_idx, Eg, 1);
    aggregate_kernel<<<(M + 7) / 8, 256>>>(out, M, 0);
}

// round 11
// speedup vs baseline: 1.2968x; 1.0127x over previous
#include <cuda_runtime.h>
#include <cuda_bf16.h>
#include <cstdint>

// Problem constants (fixed by the dataset)
#define NMAX   50000
#define EMAX   800000
#define OUT_D  128
#define DIN    256
#define NVS    256
#define NATT   16

// ---------------------------------------------------------------------------
// Device scratch
// ---------------------------------------------------------------------------
__device__ float    d_bvs[NVS];
__device__ float    d_batt[NATT];
__device__ float    d_atte[EMAX * 8];
__device__ float    d_vs[NMAX * NVS];
__device__ float    d_att[NMAX * NATT];
__device__ float    d_hidden1[NMAX * OUT_D];
__device__ int      d_deg[NMAX];
__device__ int      d_off[NMAX + 1];
__device__ int      d_cursor[NMAX];
__device__ int      d_csrcol[EMAX];
__device__ float    d_eweights[EMAX * 8];    // exp(leaky_relu(logit)) per (edge,head)

// split-bf16 operands for the tensor-core GEMMs
__device__ __nv_bfloat16 d_zhi[NMAX * DIN];
__device__ __nv_bfloat16 d_zlo[NMAX * DIN];
__device__ __nv_bfloat16 d_Wbhi[NVS * DIN];
__device__ __nv_bfloat16 d_Wblo[NVS * DIN];
__device__ __nv_bfloat16 d_Wathi[NATT * DIN];   // att weights, [n][k]
__device__ __nv_bfloat16 d_Watlo[NATT * DIN];

// ---------------------------------------------------------------------------
// Helpers
// ---------------------------------------------------------------------------
__device__ __forceinline__ uint32_t smem_u32(const void* p) {
    uint32_t a;
    asm("{ .reg .u64 t; cvta.to.shared.u64 t, %1; cvt.u32.u64 %0, t; }" : "=r"(a) : "l"(p));
    return a;
}

__device__ __forceinline__ void ldsm4(uint32_t* r, uint32_t addr) {
    asm volatile("ldmatrix.sync.aligned.m8n8.x4.shared.b16 {%0,%1,%2,%3}, [%4];"
                 : "=r"(r[0]), "=r"(r[1]), "=r"(r[2]), "=r"(r[3]) : "r"(addr));
}

__device__ __forceinline__ void mma16816(float* c, const uint32_t* a, uint32_t b0, uint32_t b1) {
    asm volatile("mma.sync.aligned.m16n8k16.row.col.f32.bf16.bf16.f32 "
                 "{%0,%1,%2,%3}, {%4,%5,%6,%7}, {%8,%9}, {%0,%1,%2,%3};"
                 : "+f"(c[0]), "+f"(c[1]), "+f"(c[2]), "+f"(c[3])
                 : "r"(a[0]), "r"(a[1]), "r"(a[2]), "r"(a[3]), "r"(b0), "r"(b1));
}

__device__ __forceinline__ void cpasync16(uint32_t dst, const void* src) {
    asm volatile("cp.async.cg.shared.global [%0], [%1], 16;" :: "r"(dst), "l"(src));
}

// packed f32x2 ops (PTX 8.6, sm_100+ base feature)
__device__ __forceinline__ void fma_f32x2(unsigned long long& acc,
                                          unsigned long long a, unsigned long long b) {
    asm("fma.rn.f32x2 %0, %1, %2, %0;" : "+l"(acc) : "l"(a), "l"(b));
}
__device__ __forceinline__ unsigned long long add_f32x2(unsigned long long a,
                                                        unsigned long long b) {
    unsigned long long r;
    asm("add.rn.f32x2 %0, %1, %2;" : "=l"(r) : "l"(a), "l"(b));
    return r;
}
__device__ __forceinline__ unsigned long long pack_f32x2(float lo, float hi) {
    unsigned long long r;
    asm("mov.b64 %0, {%1, %2};" : "=l"(r) : "f"(lo), "f"(hi));
    return r;
}
__device__ __forceinline__ void unpack_f32x2(float& lo, float& hi, unsigned long long v) {
    asm("mov.b64 {%0, %1}, %2;" : "=f"(lo), "=f"(hi) : "l"(v));
}

// ---------------------------------------------------------------------------
// Weight prep
// ---------------------------------------------------------------------------
__global__ void pack_bias_kernel(const float* __restrict__ bm, const float* __restrict__ bsk,
                                 const float* __restrict__ ba1, const float* __restrict__ ba2) {
    int i = blockIdx.x * blockDim.x + threadIdx.x;
    if (i < NVS)  d_bvs[i]  = (i < 128) ? bm[i] : bsk[i - 128];
    if (i < NATT) d_batt[i] = (i < 8) ? ba1[i] : ba2[i - 8];
}

__global__ void pack_weights_bf16_kernel(const float* __restrict__ Wm,
                                         const float* __restrict__ Wsk,
                                         const float* __restrict__ Wa1,
                                         const float* __restrict__ Wa2) {
    int i = blockIdx.x * blockDim.x + threadIdx.x;     // i = n*256 + k
    if (i < NVS * DIN) {
        int n = i >> 8, k = i & 255;
        float w = (n < 128) ? Wm[k * 128 + n] : Wsk[k * 128 + (n - 128)];
        __nv_bfloat16 hi = __float2bfloat16(w);
        __nv_bfloat16 lo = __float2bfloat16(w - __bfloat162float(hi));
        d_Wbhi[i] = hi;
        d_Wblo[i] = lo;
    }
    if (i < NATT * DIN) {
        int n = i >> 8, k = i & 255;
        float w = (n < 8) ? Wa1[k * 8 + n] : Wa2[k * 8 + (n - 8)];
        __nv_bfloat16 hi = __float2bfloat16(w);
        __nv_bfloat16 lo = __float2bfloat16(w - __bfloat162float(hi));
        d_Wathi[i] = hi;
        d_Watlo[i] = lo;
    }
}

// Convert a 128-wide fp32 node array into half of z (hi/lo split).
__global__ void convert_half_kernel(const float* __restrict__ src, int M, int half_off) {
    int idx = blockIdx.x * blockDim.x + threadIdx.x;
    if (idx >= M * 32) return;
    int row = idx >> 5, c4 = (idx & 31) * 4;
    float4 v = *(const float4*)&src[(size_t)row * 128 + c4];
    __nv_bfloat16 h[4], l[4];
    float f[4] = {v.x, v.y, v.z, v.w};
#pragma unroll
    for (int j = 0; j < 4; j++) {
        h[j] = __float2bfloat16(f[j]);
        l[j] = __float2bfloat16(f[j] - __bfloat162float(h[j]));
    }
    size_t o = (size_t)row * 256 + half_off + c4;
    *(uint2*)&d_zhi[o] = *(uint2*)h;
    *(uint2*)&d_zlo[o] = *(uint2*)l;
}

// ---------------------------------------------------------------------------
// Tensor GEMM via mma.sync, producing d_vs + d_att (fused), unchanged.
// ---------------------------------------------------------------------------
#define SSTR 72
#define SROWB (SSTR * 2)
#define OFF_AHI 0
#define OFF_ALO (128 * SROWB)
#define OFF_BHI (2 * 128 * SROWB)
#define OFF_BLO (3 * 128 * SROWB)
#define OFF_WHI (4 * 128 * SROWB)
#define OFF_WLO (OFF_WHI + 16 * SROWB)
#define GEMM_SMEM (OFF_WLO + 16 * SROWB)

__global__ __launch_bounds__(256, 1)
void gemm_vs_mma_kernel(int M) {
    extern __shared__ char smem[];
    uint32_t sb = smem_u32(smem);
    int t = threadIdx.x, wid = t >> 5, lane = t & 31;
    int warp_m = wid & 1, warp_n = wid >> 1;
    int row0 = blockIdx.x * 128, col0 = blockIdx.y * 128;
    bool blk_att = (blockIdx.y == 0);
    bool do_att = blk_att && (warp_n < 2);

    float acc[4][4][4];
#pragma unroll
    for (int a = 0; a < 4; a++)
#pragma unroll
        for (int b = 0; b < 4; b++)
#pragma unroll
            for (int c = 0; c < 4; c++) acc[a][b][c] = 0.f;
    float acc_att[4][4];
#pragma unroll
    for (int a = 0; a < 4; a++)
#pragma unroll
        for (int c = 0; c < 4; c++) acc_att[a][c] = 0.f;

    int lrow = lane & 15;
    int lcol = (lane >> 4) * 8;

    for (int kc = 0; kc < 4; kc++) {
        if (kc) __syncthreads();
        int kbase = kc * 64;
#pragma unroll
        for (int i = 0; i < 4; i++) {
            int idx = t + i * 256;
            int r = idx >> 3, k8 = (idx & 7) * 8;
            int grow = row0 + r;
            uint4 ahi = make_uint4(0, 0, 0, 0), alo = ahi;
            if (grow < M) {
                ahi = *(const uint4*)&d_zhi[(size_t)grow * 256 + kbase + k8];
                alo = *(const uint4*)&d_zlo[(size_t)grow * 256 + kbase + k8];
            }
            *(uint4*)(smem + OFF_AHI + r * SROWB + k8 * 2) = ahi;
            *(uint4*)(smem + OFF_ALO + r * SROWB + k8 * 2) = alo;
            int n = col0 + r;
            *(uint4*)(smem + OFF_BHI + r * SROWB + k8 * 2) =
                *(const uint4*)&d_Wbhi[(size_t)n * 256 + kbase + k8];
            *(uint4*)(smem + OFF_BLO + r * SROWB + k8 * 2) =
                *(const uint4*)&d_Wblo[(size_t)n * 256 + kbase + k8];
        }
        if (blk_att) {
            int r = (t >> 3) & 15, k8 = (t & 7) * 8;
            const __nv_bfloat16* src = (t < 128) ? d_Wathi : d_Watlo;
            int off = (t < 128) ? OFF_WHI : OFF_WLO;
            *(uint4*)(smem + off + r * SROWB + k8 * 2) =
                *(const uint4*)&src[(size_t)r * 256 + kbase + k8];
        }
        __syncthreads();

#pragma unroll
        for (int ks = 0; ks < 4; ks++) {
            int kofs = (ks * 16 + lcol) * 2;
            uint32_t ahi[4][4], alo[4][4];
#pragma unroll
            for (int mi = 0; mi < 4; mi++) {
                uint32_t arow = (uint32_t)(warp_m * 64 + mi * 16 + lrow);
                ldsm4(ahi[mi], sb + OFF_AHI + arow * SROWB + kofs);
                ldsm4(alo[mi], sb + OFF_ALO + arow * SROWB + kofs);
            }
            uint32_t bhi[2][4], blo[2][4];
#pragma unroll
            for (int nj = 0; nj < 2; nj++) {
                uint32_t brow = (uint32_t)(warp_n * 32 + nj * 16 + lrow);
                ldsm4(bhi[nj], sb + OFF_BHI + brow * SROWB + kofs);
                ldsm4(blo[nj], sb + OFF_BLO + brow * SROWB + kofs);
            }
#pragma unroll
            for (int mi = 0; mi < 4; mi++) {
#pragma unroll
                for (int ni = 0; ni < 4; ni++) {
                    int nj = ni >> 1, pr = ni & 1;
                    uint32_t bh0 = bhi[nj][pr], bh1 = bhi[nj][pr + 2];
                    uint32_t bl0 = blo[nj][pr], bl1 = blo[nj][pr + 2];
                    mma16816(acc[mi][ni], ahi[mi], bh0, bh1);
                    mma16816(acc[mi][ni], ahi[mi], bl0, bl1);
                    mma16816(acc[mi][ni], alo[mi], bh0, bh1);
                }
            }
            if (do_att) {
                uint32_t whi[4], wlo[4];
                ldsm4(whi, sb + OFF_WHI + (uint32_t)lrow * SROWB + kofs);
                ldsm4(wlo, sb + OFF_WLO + (uint32_t)lrow * SROWB + kofs);
                uint32_t wh0 = whi[warp_n], wh1 = whi[warp_n + 2];
                uint32_t wl0 = wlo[warp_n], wl1 = wlo[warp_n + 2];
#pragma unroll
                for (int mi = 0; mi < 4; mi++) {
                    mma16816(acc_att[mi], ahi[mi], wh0, wh1);
                    mma16816(acc_att[mi], ahi[mi], wl0, wl1);
                    mma16816(acc_att[mi], alo[mi], wh0, wh1);
                }
            }
        }
    }

#pragma unroll
    for (int mi = 0; mi < 4; mi++) {
        int rA = row0 + warp_m * 64 + mi * 16 + (lane >> 2);
        int rB = rA + 8;
#pragma unroll
        for (int ni = 0; ni < 4; ni++) {
            int col = col0 + warp_n * 32 + ni * 8 + (lane & 3) * 2;
            float2 bias = *(const float2*)&d_bvs[col];
            if (rA < M) {
                float2 o = make_float2(acc[mi][ni][0] + bias.x, acc[mi][ni][1] + bias.y);
                *(float2*)&d_vs[(size_t)rA * 256 + col] = o;
            }
            if (rB < M) {
                float2 o = make_float2(acc[mi][ni][2] + bias.x, acc[mi][ni][3] + bias.y);
                *(float2*)&d_vs[(size_t)rB * 256 + col] = o;
            }
        }
        if (do_att) {
            int col = warp_n * 8 + (lane & 3) * 2;
            float2 bias = *(const float2*)&d_batt[col];
            if (rA < M) {
                float2 o = make_float2(acc_att[mi][0] + bias.x, acc_att[mi][1] + bias.y);
                *(float2*)&d_att[(size_t)rA * 16 + col] = o;
            }
            if (rB < M) {
                float2 o = make_float2(acc_att[mi][2] + bias.x, acc_att[mi][3] + bias.y);
                *(float2*)&d_att[(size_t)rB * 16 + col] = o;
            }
        }
    }
}

// ---------------------------------------------------------------------------
// Edge-feature attention: cp.async tile streamer with packed f32x2 FMAs.
// Grid-stride over tiles; sized small (2 CTAs/SM) so it co-schedules with the
// main pass-1/pass-2 chain on a side stream.
// ---------------------------------------------------------------------------
#define EA_TILE 32
#define EA_ROWW 144

__global__ __launch_bounds__(256, 4)
void edge_att_kernel(const float* __restrict__ efts,
                     const float* __restrict__ Wae,
                     const float* __restrict__ bae, int E, int ntiles) {
    __shared__ float sbuf[2][EA_TILE * EA_ROWW];
    int t = threadIdx.x, lane = t & 31, w = t >> 5;
    int h = lane & 7, s = lane >> 3;

    unsigned long long w64[16];
#pragma unroll
    for (int j = 0; j < 16; j++)
        w64[j] = pack_f32x2(Wae[(s * 32 + 2 * j) * 8 + h],
                            Wae[(s * 32 + 2 * j + 1) * 8 + h]);
    float b = bae[h];

    uint32_t sb0 = smem_u32(&sbuf[0][0]);
    uint32_t sb1 = smem_u32(&sbuf[1][0]);

    int j = t & 31;
    int sseg = j >> 3, si = (j & 7) * 4;
    uint32_t dst_off = (uint32_t)((sseg * 36 + si) * 4);

    int ti = blockIdx.x;
    int tstep = gridDim.x;
    if (ti >= ntiles) return;

    {
        int ebase = ti * EA_TILE;
#pragma unroll
        for (int it = 0; it < 4; it++) {
            int r = it * 8 + w;
            int e = ebase + r; if (e >= E) e = E - 1;
            cpasync16(sb0 + (uint32_t)(r * EA_ROWW * 4) + dst_off,
                      efts + (size_t)e * 128 + j * 4);
        }
        asm volatile("cp.async.commit_group;" ::: "memory");
    }

    int bi = 0;
    for (; ti < ntiles; ti += tstep) {
        int tn = ti + tstep;
        if (tn < ntiles) {
            uint32_t sbn = (bi == 0) ? sb1 : sb0;
            int ebase = tn * EA_TILE;
#pragma unroll
            for (int it = 0; it < 4; it++) {
                int r = it * 8 + w;
                int e = ebase + r; if (e >= E) e = E - 1;
                cpasync16(sbn + (uint32_t)(r * EA_ROWW * 4) + dst_off,
                          efts + (size_t)e * 128 + j * 4);
            }
            asm volatile("cp.async.commit_group;" ::: "memory");
            asm volatile("cp.async.wait_group 1;" ::: "memory");
        } else {
            asm volatile("cp.async.wait_group 0;" ::: "memory");
        }
        __syncthreads();

        const float* buf = &sbuf[bi][0];
        int ebase = ti * EA_TILE;
#pragma unroll
        for (int q = 0; q < 4; q++) {
            int r = w * 4 + q;
            int e = ebase + r;
            const float* seg = buf + r * EA_ROWW + s * 36;
            unsigned long long a0 = 0ull, a1 = 0ull;
#pragma unroll
            for (int i = 0; i < 8; i++) {
                ulonglong2 p = *(const ulonglong2*)(seg + i * 4);
                fma_f32x2(a0, p.x, w64[i * 2]);
                fma_f32x2(a1, p.y, w64[i * 2 + 1]);
            }
            unsigned long long asum = add_f32x2(a0, a1);
            float flo, fhi;
            unpack_f32x2(flo, fhi, asum);
            float acc = flo + fhi;
            acc += __shfl_xor_sync(0xffffffffu, acc, 8);
            acc += __shfl_xor_sync(0xffffffffu, acc, 16);
            if (lane < 8 && e < E) d_atte[(size_t)e * 8 + lane] = acc + b;
        }
        __syncthreads();
        bi ^= 1;
    }
}

// ---------------------------------------------------------------------------
// CSR build helpers
// ---------------------------------------------------------------------------
__global__ void count_kernel(const int* __restrict__ idx, int E) {
    int e = blockIdx.x * blockDim.x + threadIdx.x;
    if (e >= E) return;
    int2 rc = ((const int2*)idx)[e];
    atomicAdd(&d_deg[rc.x], 1);
}

__global__ void scan_kernel(int n) {
    __shared__ int wsum[32];
    __shared__ int tot_s;
    int t = threadIdx.x, lane = t & 31, wid = t >> 5;
    int carry = 0;
    for (int base = 0; base < n; base += 1024) {
        int i = base + t;
        int x = (i < n) ? d_deg[i] : 0;
        int v = x;
#pragma unroll
        for (int d = 1; d < 32; d <<= 1) {
            int u = __shfl_up_sync(0xffffffffu, v, d);
            if (lane >= d) v += u;
        }
        if (lane == 31) wsum[wid] = v;
        __syncthreads();
        if (wid == 0) {
            int s = wsum[lane];
            int sv = s;
#pragma unroll
            for (int d = 1; d < 32; d <<= 1) {
                int u = __shfl_up_sync(0xffffffffu, sv, d);
                if (lane >= d) sv += u;
            }
            wsum[lane] = sv - s;
            if (lane == 31) tot_s = sv;
        }
        __syncthreads();
        int excl = carry + wsum[wid] + (v - x);
        if (i < n) { d_off[i] = excl; d_cursor[i] = excl; }
        carry += tot_s;
        __syncthreads();
    }
    if (t == 0) d_off[n] = carry;
}

// ---------------------------------------------------------------------------
// Scatter: compute exp(leaky_relu(logits)) and place at CSR position.
// ---------------------------------------------------------------------------
__global__ void scatter_logits_kernel(const int* __restrict__ idx, int E, int use_atte) {
    int e = blockIdx.x * blockDim.x + threadIdx.x;
    if (e >= E) return;
    int2 rc = ((const int2*)idx)[e];
    int row = rc.x, col = rc.y;
    int pos = atomicAdd(&d_cursor[row], 1);
    d_csrcol[pos] = col;
    const float4* pa = (const float4*)&d_att[(size_t)row * 16];
    const float4* pb = (const float4*)&d_att[(size_t)col * 16 + 8];
    float4 a0 = pa[0], a1 = pa[1];
    float4 b0 = pb[0], b1 = pb[1];
    float lg[8] = {a0.x + b0.x, a0.y + b0.y, a0.z + b0.z, a0.w + b0.w,
                   a1.x + b1.x, a1.y + b1.y, a1.z + b1.z, a1.w + b1.w};
    if (use_atte) {
        const float4* pe = (const float4*)&d_atte[(size_t)e * 8];
        float4 e0 = pe[0], e1 = pe[1];
        lg[0] += e0.x; lg[1] += e0.y; lg[2] += e0.z; lg[3] += e0.w;
        lg[4] += e1.x; lg[5] += e1.y; lg[6] += e1.z; lg[7] += e1.w;
    }
#pragma unroll
    for (int h = 0; h < 8; h++) {
        float u = lg[h];
        u = (u > 0.f) ? u : 0.01f * u;
        lg[h] = __expf(u);
    }
    *(float4*)&d_eweights[(size_t)pos * 8]     = make_float4(lg[0], lg[1], lg[2], lg[3]);
    *(float4*)&d_eweights[(size_t)pos * 8 + 4] = make_float4(lg[4], lg[5], lg[6], lg[7]);
}

// ---------------------------------------------------------------------------
// Aggregate: warp per row. Weights are precomputed exp values.
// ---------------------------------------------------------------------------
__global__ __launch_bounds__(256)
void aggregate_kernel(float* __restrict__ outp, int M, int write_z) {
    int warp = (blockIdx.x * blockDim.x + threadIdx.x) >> 5;
    if (warp >= M) return;
    int lane = threadIdx.x & 31;
    int c0 = lane * 4;
    int h = lane >> 2;
    int p = d_off[warp], pend = d_off[warp + 1];
    float s = 0.f;
    float4 acc = make_float4(0.f, 0.f, 0.f, 0.f);
    for (; p < pend; ++p) {
        int col = d_csrcol[p];
        float w = d_eweights[(size_t)p * 8 + h];
        float4 v = *(const float4*)&d_vs[(size_t)col * 256 + c0];
        s += w;
        acc.x += w * v.x; acc.y += w * v.y; acc.z += w * v.z; acc.w += w * v.w;
    }
    float4 sk = *(const float4*)&d_vs[(size_t)warp * 256 + 128 + c0];
    float inv = (s > 0.f) ? (1.f / s) : 0.f;
    float4 o;
    o.x = fmaxf(acc.x * inv + sk.x, 0.f);
    o.y = fmaxf(acc.y * inv + sk.y, 0.f);
    o.z = fmaxf(acc.z * inv + sk.z, 0.f);
    o.w = fmaxf(acc.w * inv + sk.w, 0.f);
    *(float4*)&outp[(size_t)warp * 128 + c0] = o;
    if (write_z) {
        float f[4] = {o.x, o.y, o.z, o.w};
        __nv_bfloat16 hh[4], ll[4];
#pragma unroll
        for (int jj = 0; jj < 4; jj++) {
            hh[jj] = __float2bfloat16(f[jj]);
            ll[jj] = __float2bfloat16(f[jj] - __bfloat162float(hh[jj]));
        }
        size_t zo = (size_t)warp * 256 + 128 + c0;
        *(uint2*)&d_zhi[zo] = *(uint2*)hh;
        *(uint2*)&d_zlo[zo] = *(uint2*)ll;
    }
}

// ---------------------------------------------------------------------------
// Launch. edge_att runs on a side stream (fork/join via events) so its
// 400 MB stream overlaps pass-1 / pass-2 GEMM & sparse work; it is only
// joined back right before pass-2 scatter (its sole consumer).
// ---------------------------------------------------------------------------
extern "C" void kernel_launch(void* const* d_in, const int* in_sizes, int n_in,
                              void* d_out, int out_size) {
    const float* node_fts = (const float*)d_in[0];
    const float* gkt_efts = (const float*)d_in[1];
    const float* hidden   = (const float*)d_in[2];
    const int*   cfg_idx  = (const int*)d_in[3];
    const int*   gkt_idx  = (const int*)d_in[4];
    const float* W_m    = (const float*)d_in[5];
    const float* b_m    = (const float*)d_in[6];
    const float* W_skip = (const float*)d_in[7];
    const float* b_skip = (const float*)d_in[8];
    const float* W_a1   = (const float*)d_in[9];
    const float* b_a1   = (const float*)d_in[10];
    const float* W_a2   = (const float*)d_in[11];
    const float* b_a2   = (const float*)d_in[12];
    const float* W_ae   = (const float*)d_in[13];
    const float* b_ae   = (const float*)d_in[14];
    float* out = (float*)d_out;

    int M  = in_sizes[0] / 128;
    int Ec = in_sizes[3] / 2;
    int Eg = in_sizes[4] / 2;

    float* hid1 = nullptr;
    cudaGetSymbolAddress((void**)&hid1, d_hidden1);
    int* degp = nullptr;
    cudaGetSymbolAddress((void**)&degp, d_deg);

    cudaFuncSetAttribute(gemm_vs_mma_kernel,
                         cudaFuncAttributeMaxDynamicSharedMemorySize, GEMM_SMEM);

    // Lazily-created side stream + events (host handles only; no device mem).
    static cudaStream_t s_side = nullptr;
    static cudaEvent_t  s_evFork = nullptr, s_evJoin = nullptr;
    if (s_side == nullptr) {
        cudaStream_t st = nullptr;
        cudaEvent_t  ef = nullptr, ej = nullptr;
        if (cudaStreamCreateWithFlags(&st, cudaStreamNonBlocking) == cudaSuccess &&
            cudaEventCreateWithFlags(&ef, cudaEventDisableTiming) == cudaSuccess &&
            cudaEventCreateWithFlags(&ej, cudaEventDisableTiming) == cudaSuccess) {
            s_side = st; s_evFork = ef; s_evJoin = ej;
        }
    }
    bool overlap = (s_side != nullptr);

    int ntiles = (Eg + EA_TILE - 1) / EA_TILE;

    if (overlap) {
        // fork: side stream depends on the start of this launch sequence
        cudaEventRecord(s_evFork, 0);
        cudaStreamWaitEvent(s_side, s_evFork, 0);
        edge_att_kernel<<<296, 256, 0, s_side>>>(gkt_efts, W_ae, b_ae, Eg, ntiles);
        cudaEventRecord(s_evJoin, s_side);
    } else {
        edge_att_kernel<<<1776, 256>>>(gkt_efts, W_ae, b_ae, Eg, ntiles);
    }

    pack_bias_kernel<<<1, 256>>>(b_m, b_skip, b_a1, b_a2);
    pack_weights_bf16_kernel<<<(NVS * DIN + 255) / 256, 256>>>(W_m, W_skip, W_a1, W_a2);
    convert_half_kernel<<<(M * 32 + 255) / 256, 256>>>(node_fts, M, 0);

    dim3 ggrid((M + 127) / 128, 2);

    // ---- pass 1 (cfg) ----
    convert_half_kernel<<<(M * 32 + 255) / 256, 256>>>(hidden, M, 128);
    gemm_vs_mma_kernel<<<ggrid, 256, GEMM_SMEM>>>(M);    // vs + att fused
    cudaMemsetAsync(degp, 0, (size_t)M * sizeof(int));
    count_kernel<<<(Ec + 255) / 256, 256>>>(cfg_idx, Ec);
    scan_kernel<<<1, 1024>>>(M);
    scatter_logits_kernel<<<(Ec + 255) / 256, 256>>>(cfg_idx, Ec, 0);
    aggregate_kernel<<<(M + 7) / 8, 256>>>(hid1, M, 1);

    // ---- pass 2 (gkt) ----
    gemm_vs_mma_kernel<<<ggrid, 256, GEMM_SMEM>>>(M);    // vs + att fused
    cudaMemsetAsync(degp, 0, (size_t)M * sizeof(int));
    count_kernel<<<(Eg + 255) / 256, 256>>>(gkt_idx, Eg);
    scan_kernel<<<1, 1024>>>(M);
    if (overlap) {
        cudaStreamWaitEvent(0, s_evJoin, 0);   // join: d_atte ready
    }
    scatter_logits_kernel<<<(Eg + 255) / 256, 256>>>(gkt_idx, Eg, 1);
    aggregate_kernel<<<(M + 7) / 8, 256>>>(out, M, 0);
}

// round 12
// speedup vs baseline: 1.5755x; 1.2150x over previous
#include <cuda_runtime.h>
#include <cuda_bf16.h>
#include <cstdint>

// Problem constants (fixed by the dataset)
#define NMAX   50000
#define EMAX   800000
#define OUT_D  128
#define DIN    256
#define NVS    256
#define NATT   16

// ---------------------------------------------------------------------------
// Device scratch
// ---------------------------------------------------------------------------
__device__ float    d_bvs[NVS];
__device__ float    d_batt[NATT];
__device__ float    d_atte[EMAX * 8];
__device__ float    d_vs[NMAX * NVS];
__device__ float    d_att[NMAX * NATT];
__device__ float    d_hidden1[NMAX * OUT_D];
__device__ int      d_deg[NMAX];
__device__ int      d_cursor[NMAX];
__device__ int      d_off1[NMAX + 1];
__device__ int      d_off2[NMAX + 1];
__device__ int      d_csrcol1[EMAX];
__device__ int      d_csrcol2[EMAX];
__device__ int      d_epos1[EMAX];
__device__ int      d_epos2[EMAX];
__device__ float    d_eweights[EMAX * 8];    // exp(leaky_relu(logit)) per (edge,head)

// split-bf16 operands for the tensor-core GEMMs
__device__ __nv_bfloat16 d_zhi[NMAX * DIN];
__device__ __nv_bfloat16 d_zlo[NMAX * DIN];
__device__ __nv_bfloat16 d_Wbhi[NVS * DIN];
__device__ __nv_bfloat16 d_Wblo[NVS * DIN];
__device__ __nv_bfloat16 d_Wathi[NATT * DIN];   // att weights, [n][k]
__device__ __nv_bfloat16 d_Watlo[NATT * DIN];

// ---------------------------------------------------------------------------
// Helpers
// ---------------------------------------------------------------------------
__device__ __forceinline__ uint32_t smem_u32(const void* p) {
    uint32_t a;
    asm("{ .reg .u64 t; cvta.to.shared.u64 t, %1; cvt.u32.u64 %0, t; }" : "=r"(a) : "l"(p));
    return a;
}

__device__ __forceinline__ void ldsm4(uint32_t* r, uint32_t addr) {
    asm volatile("ldmatrix.sync.aligned.m8n8.x4.shared.b16 {%0,%1,%2,%3}, [%4];"
                 : "=r"(r[0]), "=r"(r[1]), "=r"(r[2]), "=r"(r[3]) : "r"(addr));
}

__device__ __forceinline__ void mma16816(float* c, const uint32_t* a, uint32_t b0, uint32_t b1) {
    asm volatile("mma.sync.aligned.m16n8k16.row.col.f32.bf16.bf16.f32 "
                 "{%0,%1,%2,%3}, {%4,%5,%6,%7}, {%8,%9}, {%0,%1,%2,%3};"
                 : "+f"(c[0]), "+f"(c[1]), "+f"(c[2]), "+f"(c[3])
                 : "r"(a[0]), "r"(a[1]), "r"(a[2]), "r"(a[3]), "r"(b0), "r"(b1));
}

__device__ __forceinline__ void cpasync16(uint32_t dst, const void* src) {
    asm volatile("cp.async.cg.shared.global [%0], [%1], 16;" :: "r"(dst), "l"(src));
}

// packed f32x2 ops (PTX 8.6, sm_100+ base feature)
__device__ __forceinline__ void fma_f32x2(unsigned long long& acc,
                                          unsigned long long a, unsigned long long b) {
    asm("fma.rn.f32x2 %0, %1, %2, %0;" : "+l"(acc) : "l"(a), "l"(b));
}
__device__ __forceinline__ unsigned long long add_f32x2(unsigned long long a,
                                                        unsigned long long b) {
    unsigned long long r;
    asm("add.rn.f32x2 %0, %1, %2;" : "=l"(r) : "l"(a), "l"(b));
    return r;
}
__device__ __forceinline__ unsigned long long pack_f32x2(float lo, float hi) {
    unsigned long long r;
    asm("mov.b64 %0, {%1, %2};" : "=l"(r) : "f"(lo), "f"(hi));
    return r;
}
__device__ __forceinline__ void unpack_f32x2(float& lo, float& hi, unsigned long long v) {
    asm("mov.b64 {%0, %1}, %2;" : "=f"(lo), "=f"(hi) : "l"(v));
}

// ---------------------------------------------------------------------------
// Weight prep
// ---------------------------------------------------------------------------
__global__ void pack_bias_kernel(const float* __restrict__ bm, const float* __restrict__ bsk,
                                 const float* __restrict__ ba1, const float* __restrict__ ba2) {
    int i = blockIdx.x * blockDim.x + threadIdx.x;
    if (i < NVS)  d_bvs[i]  = (i < 128) ? bm[i] : bsk[i - 128];
    if (i < NATT) d_batt[i] = (i < 8) ? ba1[i] : ba2[i - 8];
}

__global__ void pack_weights_bf16_kernel(const float* __restrict__ Wm,
                                         const float* __restrict__ Wsk,
                                         const float* __restrict__ Wa1,
                                         const float* __restrict__ Wa2) {
    int i = blockIdx.x * blockDim.x + threadIdx.x;     // i = n*256 + k
    if (i < NVS * DIN) {
        int n = i >> 8, k = i & 255;
        float w = (n < 128) ? Wm[k * 128 + n] : Wsk[k * 128 + (n - 128)];
        __nv_bfloat16 hi = __float2bfloat16(w);
        __nv_bfloat16 lo = __float2bfloat16(w - __bfloat162float(hi));
        d_Wbhi[i] = hi;
        d_Wblo[i] = lo;
    }
    if (i < NATT * DIN) {
        int n = i >> 8, k = i & 255;
        float w = (n < 8) ? Wa1[k * 8 + n] : Wa2[k * 8 + (n - 8)];
        __nv_bfloat16 hi = __float2bfloat16(w);
        __nv_bfloat16 lo = __float2bfloat16(w - __bfloat162float(hi));
        d_Wathi[i] = hi;
        d_Watlo[i] = lo;
    }
}

// Convert a 128-wide fp32 node array into half of z (hi/lo split).
__global__ void convert_half_kernel(const float* __restrict__ src, int M, int half_off) {
    int idx = blockIdx.x * blockDim.x + threadIdx.x;
    if (idx >= M * 32) return;
    int row = idx >> 5, c4 = (idx & 31) * 4;
    float4 v = *(const float4*)&src[(size_t)row * 128 + c4];
    __nv_bfloat16 h[4], l[4];
    float f[4] = {v.x, v.y, v.z, v.w};
#pragma unroll
    for (int j = 0; j < 4; j++) {
        h[j] = __float2bfloat16(f[j]);
        l[j] = __float2bfloat16(f[j] - __bfloat162float(h[j]));
    }
    size_t o = (size_t)row * 256 + half_off + c4;
    *(uint2*)&d_zhi[o] = *(uint2*)h;
    *(uint2*)&d_zlo[o] = *(uint2*)l;
}

// ---------------------------------------------------------------------------
// Tensor GEMM via mma.sync, producing d_vs + d_att (fused), unchanged.
// ---------------------------------------------------------------------------
#define SSTR 72
#define SROWB (SSTR * 2)
#define OFF_AHI 0
#define OFF_ALO (128 * SROWB)
#define OFF_BHI (2 * 128 * SROWB)
#define OFF_BLO (3 * 128 * SROWB)
#define OFF_WHI (4 * 128 * SROWB)
#define OFF_WLO (OFF_WHI + 16 * SROWB)
#define GEMM_SMEM (OFF_WLO + 16 * SROWB)

__global__ __launch_bounds__(256, 1)
void gemm_vs_mma_kernel(int M) {
    extern __shared__ char smem[];
    uint32_t sb = smem_u32(smem);
    int t = threadIdx.x, wid = t >> 5, lane = t & 31;
    int warp_m = wid & 1, warp_n = wid >> 1;
    int row0 = blockIdx.x * 128, col0 = blockIdx.y * 128;
    bool blk_att = (blockIdx.y == 0);
    bool do_att = blk_att && (warp_n < 2);

    float acc[4][4][4];
#pragma unroll
    for (int a = 0; a < 4; a++)
#pragma unroll
        for (int b = 0; b < 4; b++)
#pragma unroll
            for (int c = 0; c < 4; c++) acc[a][b][c] = 0.f;
    float acc_att[4][4];
#pragma unroll
    for (int a = 0; a < 4; a++)
#pragma unroll
        for (int c = 0; c < 4; c++) acc_att[a][c] = 0.f;

    int lrow = lane & 15;
    int lcol = (lane >> 4) * 8;

    for (int kc = 0; kc < 4; kc++) {
        if (kc) __syncthreads();
        int kbase = kc * 64;
#pragma unroll
        for (int i = 0; i < 4; i++) {
            int idx = t + i * 256;
            int r = idx >> 3, k8 = (idx & 7) * 8;
            int grow = row0 + r;
            uint4 ahi = make_uint4(0, 0, 0, 0), alo = ahi;
            if (grow < M) {
                ahi = *(const uint4*)&d_zhi[(size_t)grow * 256 + kbase + k8];
                alo = *(const uint4*)&d_zlo[(size_t)grow * 256 + kbase + k8];
            }
            *(uint4*)(smem + OFF_AHI + r * SROWB + k8 * 2) = ahi;
            *(uint4*)(smem + OFF_ALO + r * SROWB + k8 * 2) = alo;
            int n = col0 + r;
            *(uint4*)(smem + OFF_BHI + r * SROWB + k8 * 2) =
                *(const uint4*)&d_Wbhi[(size_t)n * 256 + kbase + k8];
            *(uint4*)(smem + OFF_BLO + r * SROWB + k8 * 2) =
                *(const uint4*)&d_Wblo[(size_t)n * 256 + kbase + k8];
        }
        if (blk_att) {
            int r = (t >> 3) & 15, k8 = (t & 7) * 8;
            const __nv_bfloat16* src = (t < 128) ? d_Wathi : d_Watlo;
            int off = (t < 128) ? OFF_WHI : OFF_WLO;
            *(uint4*)(smem + off + r * SROWB + k8 * 2) =
                *(const uint4*)&src[(size_t)r * 256 + kbase + k8];
        }
        __syncthreads();

#pragma unroll
        for (int ks = 0; ks < 4; ks++) {
            int kofs = (ks * 16 + lcol) * 2;
            uint32_t ahi[4][4], alo[4][4];
#pragma unroll
            for (int mi = 0; mi < 4; mi++) {
                uint32_t arow = (uint32_t)(warp_m * 64 + mi * 16 + lrow);
                ldsm4(ahi[mi], sb + OFF_AHI + arow * SROWB + kofs);
                ldsm4(alo[mi], sb + OFF_ALO + arow * SROWB + kofs);
            }
            uint32_t bhi[2][4], blo[2][4];
#pragma unroll
            for (int nj = 0; nj < 2; nj++) {
                uint32_t brow = (uint32_t)(warp_n * 32 + nj * 16 + lrow);
                ldsm4(bhi[nj], sb + OFF_BHI + brow * SROWB + kofs);
                ldsm4(blo[nj], sb + OFF_BLO + brow * SROWB + kofs);
            }
#pragma unroll
            for (int mi = 0; mi < 4; mi++) {
#pragma unroll
                for (int ni = 0; ni < 4; ni++) {
                    int nj = ni >> 1, pr = ni & 1;
                    uint32_t bh0 = bhi[nj][pr], bh1 = bhi[nj][pr + 2];
                    uint32_t bl0 = blo[nj][pr], bl1 = blo[nj][pr + 2];
                    mma16816(acc[mi][ni], ahi[mi], bh0, bh1);
                    mma16816(acc[mi][ni], ahi[mi], bl0, bl1);
                    mma16816(acc[mi][ni], alo[mi], bh0, bh1);
                }
            }
            if (do_att) {
                uint32_t whi[4], wlo[4];
                ldsm4(whi, sb + OFF_WHI + (uint32_t)lrow * SROWB + kofs);
                ldsm4(wlo, sb + OFF_WLO + (uint32_t)lrow * SROWB + kofs);
                uint32_t wh0 = whi[warp_n], wh1 = whi[warp_n + 2];
                uint32_t wl0 = wlo[warp_n], wl1 = wlo[warp_n + 2];
#pragma unroll
                for (int mi = 0; mi < 4; mi++) {
                    mma16816(acc_att[mi], ahi[mi], wh0, wh1);
                    mma16816(acc_att[mi], ahi[mi], wl0, wl1);
                    mma16816(acc_att[mi], alo[mi], wh0, wh1);
                }
            }
        }
    }

#pragma unroll
    for (int mi = 0; mi < 4; mi++) {
        int rA = row0 + warp_m * 64 + mi * 16 + (lane >> 2);
        int rB = rA + 8;
#pragma unroll
        for (int ni = 0; ni < 4; ni++) {
            int col = col0 + warp_n * 32 + ni * 8 + (lane & 3) * 2;
            float2 bias = *(const float2*)&d_bvs[col];
            if (rA < M) {
                float2 o = make_float2(acc[mi][ni][0] + bias.x, acc[mi][ni][1] + bias.y);
                *(float2*)&d_vs[(size_t)rA * 256 + col] = o;
            }
            if (rB < M) {
                float2 o = make_float2(acc[mi][ni][2] + bias.x, acc[mi][ni][3] + bias.y);
                *(float2*)&d_vs[(size_t)rB * 256 + col] = o;
            }
        }
        if (do_att) {
            int col = warp_n * 8 + (lane & 3) * 2;
            float2 bias = *(const float2*)&d_batt[col];
            if (rA < M) {
                float2 o = make_float2(acc_att[mi][0] + bias.x, acc_att[mi][1] + bias.y);
                *(float2*)&d_att[(size_t)rA * 16 + col] = o;
            }
            if (rB < M) {
                float2 o = make_float2(acc_att[mi][2] + bias.x, acc_att[mi][3] + bias.y);
                *(float2*)&d_att[(size_t)rB * 16 + col] = o;
            }
        }
    }
}

// ---------------------------------------------------------------------------
// Edge-feature attention: cp.async tile streamer with packed f32x2 FMAs.
// ---------------------------------------------------------------------------
#define EA_TILE 32
#define EA_ROWW 144

__global__ __launch_bounds__(256, 4)
void edge_att_kernel(const float* __restrict__ efts,
                     const float* __restrict__ Wae,
                     const float* __restrict__ bae, int E, int ntiles) {
    __shared__ float sbuf[2][EA_TILE * EA_ROWW];
    int t = threadIdx.x, lane = t & 31, w = t >> 5;
    int h = lane & 7, s = lane >> 3;

    unsigned long long w64[16];
#pragma unroll
    for (int j = 0; j < 16; j++)
        w64[j] = pack_f32x2(Wae[(s * 32 + 2 * j) * 8 + h],
                            Wae[(s * 32 + 2 * j + 1) * 8 + h]);
    float b = bae[h];

    uint32_t sb0 = smem_u32(&sbuf[0][0]);
    uint32_t sb1 = smem_u32(&sbuf[1][0]);

    int j = t & 31;
    int sseg = j >> 3, si = (j & 7) * 4;
    uint32_t dst_off = (uint32_t)((sseg * 36 + si) * 4);

    int ti = blockIdx.x;
    int tstep = gridDim.x;
    if (ti >= ntiles) return;

    {
        int ebase = ti * EA_TILE;
#pragma unroll
        for (int it = 0; it < 4; it++) {
            int r = it * 8 + w;
            int e = ebase + r; if (e >= E) e = E - 1;
            cpasync16(sb0 + (uint32_t)(r * EA_ROWW * 4) + dst_off,
                      efts + (size_t)e * 128 + j * 4);
        }
        asm volatile("cp.async.commit_group;" ::: "memory");
    }

    int bi = 0;
    for (; ti < ntiles; ti += tstep) {
        int tn = ti + tstep;
        if (tn < ntiles) {
            uint32_t sbn = (bi == 0) ? sb1 : sb0;
            int ebase = tn * EA_TILE;
#pragma unroll
            for (int it = 0; it < 4; it++) {
                int r = it * 8 + w;
                int e = ebase + r; if (e >= E) e = E - 1;
                cpasync16(sbn + (uint32_t)(r * EA_ROWW * 4) + dst_off,
                          efts + (size_t)e * 128 + j * 4);
            }
            asm volatile("cp.async.commit_group;" ::: "memory");
            asm volatile("cp.async.wait_group 1;" ::: "memory");
        } else {
            asm volatile("cp.async.wait_group 0;" ::: "memory");
        }
        __syncthreads();

        const float* buf = &sbuf[bi][0];
        int ebase = ti * EA_TILE;
#pragma unroll
        for (int q = 0; q < 4; q++) {
            int r = w * 4 + q;
            int e = ebase + r;
            const float* seg = buf + r * EA_ROWW + s * 36;
            unsigned long long a0 = 0ull, a1 = 0ull;
#pragma unroll
            for (int i = 0; i < 8; i++) {
                ulonglong2 p = *(const ulonglong2*)(seg + i * 4);
                fma_f32x2(a0, p.x, w64[i * 2]);
                fma_f32x2(a1, p.y, w64[i * 2 + 1]);
            }
            unsigned long long asum = add_f32x2(a0, a1);
            float flo, fhi;
            unpack_f32x2(flo, fhi, asum);
            float acc = flo + fhi;
            acc += __shfl_xor_sync(0xffffffffu, acc, 8);
            acc += __shfl_xor_sync(0xffffffffu, acc, 16);
            if (lane < 8 && e < E) d_atte[(size_t)e * 8 + lane] = acc + b;
        }
        __syncthreads();
        bi ^= 1;
    }
}

// ---------------------------------------------------------------------------
// CSR build (runs on a side stream; depends only on the index arrays)
// ---------------------------------------------------------------------------
__global__ void count_kernel(const int* __restrict__ idx, int E) {
    int e = blockIdx.x * blockDim.x + threadIdx.x;
    if (e >= E) return;
    int2 rc = ((const int2*)idx)[e];
    atomicAdd(&d_deg[rc.x], 1);
}

__global__ void scan_kernel(int n, int* __restrict__ off) {
    __shared__ int wsum[32];
    __shared__ int tot_s;
    int t = threadIdx.x, lane = t & 31, wid = t >> 5;
    int carry = 0;
    for (int base = 0; base < n; base += 1024) {
        int i = base + t;
        int x = (i < n) ? d_deg[i] : 0;
        int v = x;
#pragma unroll
        for (int d = 1; d < 32; d <<= 1) {
            int u = __shfl_up_sync(0xffffffffu, v, d);
            if (lane >= d) v += u;
        }
        if (lane == 31) wsum[wid] = v;
        __syncthreads();
        if (wid == 0) {
            int s = wsum[lane];
            int sv = s;
#pragma unroll
            for (int d = 1; d < 32; d <<= 1) {
                int u = __shfl_up_sync(0xffffffffu, sv, d);
                if (lane >= d) sv += u;
            }
            wsum[lane] = sv - s;
            if (lane == 31) tot_s = sv;
        }
        __syncthreads();
        int excl = carry + wsum[wid] + (v - x);
        if (i < n) { off[i] = excl; d_cursor[i] = excl; }
        carry += tot_s;
        __syncthreads();
    }
    if (t == 0) off[n] = carry;
}

// Assign each edge its CSR slot; record col and slot.
__global__ void pos_kernel(const int* __restrict__ idx, int E,
                           int* __restrict__ csrcol, int* __restrict__ epos) {
    int e = blockIdx.x * blockDim.x + threadIdx.x;
    if (e >= E) return;
    int2 rc = ((const int2*)idx)[e];
    int pos = atomicAdd(&d_cursor[rc.x], 1);
    csrcol[pos] = rc.y;
    epos[e] = pos;
}

// ---------------------------------------------------------------------------
// Scatter: compute exp(leaky_relu(logits)) into the precomputed CSR slot.
// No atomics (epos precomputed on side stream).
// ---------------------------------------------------------------------------
__global__ void scatter_logits_kernel(const int* __restrict__ idx, int E, int use_atte,
                                      const int* __restrict__ epos) {
    int e = blockIdx.x * blockDim.x + threadIdx.x;
    if (e >= E) return;
    int2 rc = ((const int2*)idx)[e];
    int row = rc.x, col = rc.y;
    int pos = epos[e];
    const float4* pa = (const float4*)&d_att[(size_t)row * 16];
    const float4* pb = (const float4*)&d_att[(size_t)col * 16 + 8];
    float4 a0 = pa[0], a1 = pa[1];
    float4 b0 = pb[0], b1 = pb[1];
    float lg[8] = {a0.x + b0.x, a0.y + b0.y, a0.z + b0.z, a0.w + b0.w,
                   a1.x + b1.x, a1.y + b1.y, a1.z + b1.z, a1.w + b1.w};
    if (use_atte) {
        const float4* pe = (const float4*)&d_atte[(size_t)e * 8];
        float4 e0 = pe[0], e1 = pe[1];
        lg[0] += e0.x; lg[1] += e0.y; lg[2] += e0.z; lg[3] += e0.w;
        lg[4] += e1.x; lg[5] += e1.y; lg[6] += e1.z; lg[7] += e1.w;
    }
#pragma unroll
    for (int h = 0; h < 8; h++) {
        float u = lg[h];
        u = (u > 0.f) ? u : 0.01f * u;
        lg[h] = __expf(u);
    }
    *(float4*)&d_eweights[(size_t)pos * 8]     = make_float4(lg[0], lg[1], lg[2], lg[3]);
    *(float4*)&d_eweights[(size_t)pos * 8 + 4] = make_float4(lg[4], lg[5], lg[6], lg[7]);
}

// ---------------------------------------------------------------------------
// Aggregate: warp per row. Weights are precomputed exp values.
// ---------------------------------------------------------------------------
__global__ __launch_bounds__(256)
void aggregate_kernel(float* __restrict__ outp, int M, int write_z,
                      const int* __restrict__ off, const int* __restrict__ csrcol) {
    int warp = (blockIdx.x * blockDim.x + threadIdx.x) >> 5;
    if (warp >= M) return;
    int lane = threadIdx.x & 31;
    int c0 = lane * 4;
    int h = lane >> 2;
    int p = off[warp], pend = off[warp + 1];
    float s = 0.f;
    float4 acc = make_float4(0.f, 0.f, 0.f, 0.f);
    for (; p < pend; ++p) {
        int col = csrcol[p];
        float w = d_eweights[(size_t)p * 8 + h];
        float4 v = *(const float4*)&d_vs[(size_t)col * 256 + c0];
        s += w;
        acc.x += w * v.x; acc.y += w * v.y; acc.z += w * v.z; acc.w += w * v.w;
    }
    float4 sk = *(const float4*)&d_vs[(size_t)warp * 256 + 128 + c0];
    float inv = (s > 0.f) ? (1.f / s) : 0.f;
    float4 o;
    o.x = fmaxf(acc.x * inv + sk.x, 0.f);
    o.y = fmaxf(acc.y * inv + sk.y, 0.f);
    o.z = fmaxf(acc.z * inv + sk.z, 0.f);
    o.w = fmaxf(acc.w * inv + sk.w, 0.f);
    *(float4*)&outp[(size_t)warp * 128 + c0] = o;
    if (write_z) {
        float f[4] = {o.x, o.y, o.z, o.w};
        __nv_bfloat16 hh[4], ll[4];
#pragma unroll
        for (int jj = 0; jj < 4; jj++) {
            hh[jj] = __float2bfloat16(f[jj]);
            ll[jj] = __float2bfloat16(f[jj] - __bfloat162float(hh[jj]));
        }
        size_t zo = (size_t)warp * 256 + 128 + c0;
        *(uint2*)&d_zhi[zo] = *(uint2*)hh;
        *(uint2*)&d_zlo[zo] = *(uint2*)ll;
    }
}

// ---------------------------------------------------------------------------
// Launch. Two side streams:
//   s1: edge_att (consumed only by pass-2 scatter)
//   s2: CSR builds for BOTH passes (depend only on index arrays)
// Main stream: converts -> gemm1 -> scatter1 -> aggregate1 -> gemm2 ->
//              scatter2 -> aggregate2.
// ---------------------------------------------------------------------------
extern "C" void kernel_launch(void* const* d_in, const int* in_sizes, int n_in,
                              void* d_out, int out_size) {
    const float* node_fts = (const float*)d_in[0];
    const float* gkt_efts = (const float*)d_in[1];
    const float* hidden   = (const float*)d_in[2];
    const int*   cfg_idx  = (const int*)d_in[3];
    const int*   gkt_idx  = (const int*)d_in[4];
    const float* W_m    = (const float*)d_in[5];
    const float* b_m    = (const float*)d_in[6];
    const float* W_skip = (const float*)d_in[7];
    const float* b_skip = (const float*)d_in[8];
    const float* W_a1   = (const float*)d_in[9];
    const float* b_a1   = (const float*)d_in[10];
    const float* W_a2   = (const float*)d_in[11];
    const float* b_a2   = (const float*)d_in[12];
    const float* W_ae   = (const float*)d_in[13];
    const float* b_ae   = (const float*)d_in[14];
    float* out = (float*)d_out;

    int M  = in_sizes[0] / 128;
    int Ec = in_sizes[3] / 2;
    int Eg = in_sizes[4] / 2;

    float* hid1 = nullptr;  cudaGetSymbolAddress((void**)&hid1, d_hidden1);
    int* degp = nullptr;    cudaGetSymbolAddress((void**)&degp, d_deg);
    int* off1p = nullptr;   cudaGetSymbolAddress((void**)&off1p, d_off1);
    int* off2p = nullptr;   cudaGetSymbolAddress((void**)&off2p, d_off2);
    int* col1p = nullptr;   cudaGetSymbolAddress((void**)&col1p, d_csrcol1);
    int* col2p = nullptr;   cudaGetSymbolAddress((void**)&col2p, d_csrcol2);
    int* ep1p = nullptr;    cudaGetSymbolAddress((void**)&ep1p, d_epos1);
    int* ep2p = nullptr;    cudaGetSymbolAddress((void**)&ep2p, d_epos2);

    cudaFuncSetAttribute(gemm_vs_mma_kernel,
                         cudaFuncAttributeMaxDynamicSharedMemorySize, GEMM_SMEM);

    // Lazily-created side streams + events (host handles only).
    static cudaStream_t s1 = nullptr, s2 = nullptr;
    static cudaEvent_t  evFork = nullptr, evAtte = nullptr, evCsr1 = nullptr, evCsr2 = nullptr;
    if (s1 == nullptr) {
        cudaStream_t a = nullptr, b = nullptr;
        cudaEvent_t e0 = nullptr, e1 = nullptr, e2 = nullptr, e3 = nullptr;
        if (cudaStreamCreateWithFlags(&a, cudaStreamNonBlocking) == cudaSuccess &&
            cudaStreamCreateWithFlags(&b, cudaStreamNonBlocking) == cudaSuccess &&
            cudaEventCreateWithFlags(&e0, cudaEventDisableTiming) == cudaSuccess &&
            cudaEventCreateWithFlags(&e1, cudaEventDisableTiming) == cudaSuccess &&
            cudaEventCreateWithFlags(&e2, cudaEventDisableTiming) == cudaSuccess &&
            cudaEventCreateWithFlags(&e3, cudaEventDisableTiming) == cudaSuccess) {
            s1 = a; s2 = b; evFork = e0; evAtte = e1; evCsr1 = e2; evCsr2 = e3;
        }
    }
    bool overlap = (s1 != nullptr);

    int ntiles = (Eg + EA_TILE - 1) / EA_TILE;

    if (overlap) {
        cudaEventRecord(evFork, 0);
        cudaStreamWaitEvent(s1, evFork, 0);
        cudaStreamWaitEvent(s2, evFork, 0);

        // s1: edge attention (full-size grid, fair-share competition)
        edge_att_kernel<<<1776, 256, 0, s1>>>(gkt_efts, W_ae, b_ae, Eg, ntiles);
        cudaEventRecord(evAtte, s1);

        // s2: CSR builds for both passes
        cudaMemsetAsync(degp, 0, (size_t)M * sizeof(int), s2);
        count_kernel<<<(Ec + 255) / 256, 256, 0, s2>>>(cfg_idx, Ec);
        scan_kernel<<<1, 1024, 0, s2>>>(M, off1p);
        pos_kernel<<<(Ec + 255) / 256, 256, 0, s2>>>(cfg_idx, Ec, col1p, ep1p);
        cudaEventRecord(evCsr1, s2);
        cudaMemsetAsync(degp, 0, (size_t)M * sizeof(int), s2);
        count_kernel<<<(Eg + 255) / 256, 256, 0, s2>>>(gkt_idx, Eg);
        scan_kernel<<<1, 1024, 0, s2>>>(M, off2p);
        pos_kernel<<<(Eg + 255) / 256, 256, 0, s2>>>(gkt_idx, Eg, col2p, ep2p);
        cudaEventRecord(evCsr2, s2);
    } else {
        edge_att_kernel<<<1776, 256>>>(gkt_efts, W_ae, b_ae, Eg, ntiles);
        cudaMemsetAsync(degp, 0, (size_t)M * sizeof(int));
        count_kernel<<<(Ec + 255) / 256, 256>>>(cfg_idx, Ec);
        scan_kernel<<<1, 1024>>>(M, off1p);
        pos_kernel<<<(Ec + 255) / 256, 256>>>(cfg_idx, Ec, col1p, ep1p);
        cudaMemsetAsync(degp, 0, (size_t)M * sizeof(int));
        count_kernel<<<(Eg + 255) / 256, 256>>>(gkt_idx, Eg);
        scan_kernel<<<1, 1024>>>(M, off2p);
        pos_kernel<<<(Eg + 255) / 256, 256>>>(gkt_idx, Eg, col2p, ep2p);
    }

    // ---- main chain ----
    pack_bias_kernel<<<1, 256>>>(b_m, b_skip, b_a1, b_a2);
    pack_weights_bf16_kernel<<<(NVS * DIN + 255) / 256, 256>>>(W_m, W_skip, W_a1, W_a2);
    convert_half_kernel<<<(M * 32 + 255) / 256, 256>>>(node_fts, M, 0);
    convert_half_kernel<<<(M * 32 + 255) / 256, 256>>>(hidden, M, 128);

    dim3 ggrid((M + 127) / 128, 2);

    // pass 1 (cfg)
    gemm_vs_mma_kernel<<<ggrid, 256, GEMM_SMEM>>>(M);
    if (overlap) cudaStreamWaitEvent(0, evCsr1, 0);
    scatter_logits_kernel<<<(Ec + 255) / 256, 256>>>(cfg_idx, Ec, 0, ep1p);
    aggregate_kernel<<<(M + 7) / 8, 256>>>(hid1, M, 1, off1p, col1p);

    // pass 2 (gkt)
    gemm_vs_mma_kernel<<<ggrid, 256, GEMM_SMEM>>>(M);
    if (overlap) {
        cudaStreamWaitEvent(0, evCsr2, 0);
        cudaStreamWaitEvent(0, evAtte, 0);
    }
    scatter_logits_kernel<<<(Eg + 255) / 256, 256>>>(gkt_idx, Eg, 1, ep2p);
    aggregate_kernel<<<(M + 7) / 8, 256>>>(out, M, 0, off2p, col2p);
}